// round 6
// baseline (speedup 1.0000x reference)
#include <cuda_runtime.h>

#define NN    20000
#define BG    100
#define PERN  200
#define EE    320000
#define ETOT  340000
#define FIN   32
#define NH    10
#define C1    320
#define DOUT  128
#define NEG_SLOPE 0.2f

// ---------------- scratch ----------------------------------------------------
__device__ float g_P   [FIN * 20];          // fused score projection [32][20]
__device__ float g_S1S [NN * NH];
__device__ float g_S1D [NN * NH];
__device__ float g_AGG [NN * C1];           // per-head aggregated raw feats
__device__ float g_X1  [NN * C1];           // layer-1 output after elu
__device__ float g_XW2 [NN * DOUT];
__device__ float g_S2S [NN];
__device__ float g_S2D [NN];
__device__ float g_X2E [(NN + BG) * DOUT];  // node rows + pooled rows
__device__ int   g_DEG[NN];
__device__ int   g_ROWPTR[NN + 1];
__device__ int   g_ROWCUR[NN];
__device__ int   g_ESRT[ETOT];

__device__ __forceinline__ float leakyf(float x) { return x > 0.f ? x : NEG_SLOPE * x; }
__device__ __forceinline__ float eluf(float x)   { return x > 0.f ? x : __expf(x) - 1.f; }

__device__ __forceinline__ unsigned f2tf(float x) {
    unsigned r;
    asm("cvt.rna.tf32.f32 %0, %1;" : "=r"(r) : "f"(x));
    return r;
}
__device__ __forceinline__ void mma8(float* d, const unsigned* a, const unsigned* b) {
    asm volatile(
        "mma.sync.aligned.m16n8k8.row.col.f32.tf32.tf32.f32 "
        "{%0,%1,%2,%3}, {%4,%5,%6,%7}, {%8,%9}, {%0,%1,%2,%3};\n"
        : "+f"(d[0]), "+f"(d[1]), "+f"(d[2]), "+f"(d[3])
        : "r"(a[0]), "r"(a[1]), "r"(a[2]), "r"(a[3]), "r"(b[0]), "r"(b[1]));
}

// ---------------- TF32 tensor-core GEMM (3xTF32) ------------------------------
template <int MODE>   // 0 plain, 1 bias+relu
__global__ __launch_bounds__(256)
void k_tgemm(const float* __restrict__ A, const float* __restrict__ B,
             const float* __restrict__ bias, float* __restrict__ C,
             int M, int N, int K) {
    __shared__ float As[16][136];
    __shared__ float Bs[16][136];
    const int tid  = threadIdx.x;
    const int lane = tid & 31;
    const int wid  = tid >> 5;
    const int qr   = lane >> 2;
    const int qc   = lane & 3;
    const int wm   = (wid & 3) * 32;
    const int wn   = (wid >> 2) * 64;
    const int row0 = blockIdx.x * 128;
    const int col0 = blockIdx.y * 128;

    float acc[2][8][4];
#pragma unroll
    for (int mf = 0; mf < 2; mf++)
#pragma unroll
        for (int nf = 0; nf < 8; nf++)
#pragma unroll
            for (int i = 0; i < 4; i++) acc[mf][nf][i] = 0.f;

    for (int k0 = 0; k0 < K; k0 += 16) {
#pragma unroll
        for (int i = 0; i < 2; i++) {
            int f = tid + i * 256;
            int r = f >> 2, c4 = (f & 3) * 4;
            float4 v = {0.f, 0.f, 0.f, 0.f};
            if (row0 + r < M)
                v = *reinterpret_cast<const float4*>(A + (size_t)(row0 + r) * K + k0 + c4);
            As[c4 + 0][r] = v.x; As[c4 + 1][r] = v.y;
            As[c4 + 2][r] = v.z; As[c4 + 3][r] = v.w;
        }
#pragma unroll
        for (int i = 0; i < 2; i++) {
            int f = tid + i * 256;
            int kk = f >> 5, c4 = (f & 31) * 4;
            float4 v = {0.f, 0.f, 0.f, 0.f};
            const float* src = B + (size_t)(k0 + kk) * N + col0 + c4;
            if (col0 + c4 + 3 < N) {
                v = *reinterpret_cast<const float4*>(src);
            } else {
                if (col0 + c4 + 0 < N) v.x = src[0];
                if (col0 + c4 + 1 < N) v.y = src[1];
                if (col0 + c4 + 2 < N) v.z = src[2];
                if (col0 + c4 + 3 < N) v.w = src[3];
            }
            *reinterpret_cast<float4*>(&Bs[kk][c4]) = v;
        }
        __syncthreads();

#pragma unroll
        for (int ks = 0; ks < 16; ks += 8) {
            unsigned ah[2][4], al[2][4], bh[8][2], bl[8][2];
#pragma unroll
            for (int mf = 0; mf < 2; mf++) {
                int mb = wm + mf * 16 + qr;
                float x0 = As[ks + qc][mb];
                float x1 = As[ks + qc][mb + 8];
                float x2 = As[ks + qc + 4][mb];
                float x3 = As[ks + qc + 4][mb + 8];
                ah[mf][0] = f2tf(x0); al[mf][0] = f2tf(x0 - __uint_as_float(ah[mf][0]));
                ah[mf][1] = f2tf(x1); al[mf][1] = f2tf(x1 - __uint_as_float(ah[mf][1]));
                ah[mf][2] = f2tf(x2); al[mf][2] = f2tf(x2 - __uint_as_float(ah[mf][2]));
                ah[mf][3] = f2tf(x3); al[mf][3] = f2tf(x3 - __uint_as_float(ah[mf][3]));
            }
#pragma unroll
            for (int nf = 0; nf < 8; nf++) {
                int nb = wn + nf * 8 + qr;
                float y0 = Bs[ks + qc][nb];
                float y1 = Bs[ks + qc + 4][nb];
                bh[nf][0] = f2tf(y0); bl[nf][0] = f2tf(y0 - __uint_as_float(bh[nf][0]));
                bh[nf][1] = f2tf(y1); bl[nf][1] = f2tf(y1 - __uint_as_float(bh[nf][1]));
            }
#pragma unroll
            for (int mf = 0; mf < 2; mf++)
#pragma unroll
                for (int nf = 0; nf < 8; nf++) {
                    mma8(acc[mf][nf], ah[mf], bh[nf]);
                    mma8(acc[mf][nf], al[mf], bh[nf]);
                    mma8(acc[mf][nf], ah[mf], bl[nf]);
                }
        }
        __syncthreads();
    }

#pragma unroll
    for (int mf = 0; mf < 2; mf++) {
        int r0 = row0 + wm + mf * 16 + qr;
#pragma unroll
        for (int nf = 0; nf < 8; nf++) {
            int c = col0 + wn + nf * 8 + 2 * qc;
            float2 v0 = {acc[mf][nf][0], acc[mf][nf][1]};
            float2 v1 = {acc[mf][nf][2], acc[mf][nf][3]};
            if (MODE == 1) {
                float bc0 = bias[c], bc1 = bias[c + 1];
                v0.x = fmaxf(v0.x + bc0, 0.f); v0.y = fmaxf(v0.y + bc1, 0.f);
                v1.x = fmaxf(v1.x + bc0, 0.f); v1.y = fmaxf(v1.y + bc1, 0.f);
            }
            if (r0 < M && c + 1 < N)
                *reinterpret_cast<float2*>(C + (size_t)r0 * N + c) = v0;
            if (r0 + 8 < M && c + 1 < N)
                *reinterpret_cast<float2*>(C + (size_t)(r0 + 8) * N + c) = v1;
        }
    }
}

// ---------------- P = W1-projected attention vectors [32][20] ----------------
__global__ void k_prep(const float* __restrict__ W1, const float* __restrict__ a1s,
                       const float* __restrict__ a1d) {
    int t = threadIdx.x;
    if (t >= FIN * 20) return;
    int k = t / 20, c = t % 20;
    int h = (c < NH) ? c : c - NH;
    const float* av = (c < NH) ? a1s : a1d;
    float s = 0.f;
#pragma unroll
    for (int f = 0; f < FIN; f++)
        s += W1[k * C1 + h * FIN + f] * av[h * FIN + f];
    g_P[k * 20 + c] = s;
}

// ---------------- per-node layer-1 scores: feats @ P --------------------------
__global__ void k_scores(const float* __restrict__ feats) {
    __shared__ float Ps[FIN][20];
    __shared__ float xs[8][FIN];
    int tid = threadIdx.x;
    int wid = tid >> 5, lane = tid & 31;
    for (int idx = tid; idx < FIN * 20; idx += 256)      // FIXED: strided load
        Ps[idx / 20][idx % 20] = g_P[idx];
    int n = blockIdx.x * 8 + wid;
    if (n < NN) xs[wid][lane] = feats[n * FIN + lane];
    __syncthreads();
    if (n >= NN || lane >= 20) return;
    float s = 0.f;
#pragma unroll
    for (int k = 0; k < FIN; k++)
        s += xs[wid][k] * Ps[k][lane];
    if (lane < NH) g_S1S[n * NH + lane] = s;
    else           g_S1D[n * NH + lane - NH] = s;
}

// ---------------- CSR build ---------------------------------------------------
__global__ void k_count(const int* __restrict__ edst) {
    int e = blockIdx.x * blockDim.x + threadIdx.x;
    if (e < EE) atomicAdd(&g_DEG[edst[e]], 1);
}

__global__ void k_scan() {
    const int CH = 20;
    __shared__ int sh[1024];
    int t = threadIdx.x;
    int start = t * CH;
    int s = 0;
    for (int i = 0; i < CH; i++) {
        int idx = start + i;
        if (idx < NN) s += g_DEG[idx] + 1;
    }
    sh[t] = s;
    __syncthreads();
    for (int off = 1; off < 1024; off <<= 1) {
        int v = (t >= off) ? sh[t - off] : 0;
        __syncthreads();
        sh[t] += v;
        __syncthreads();
    }
    int run = (t > 0) ? sh[t - 1] : 0;
    for (int i = 0; i < CH; i++) {
        int idx = start + i;
        if (idx < NN) {
            g_ROWPTR[idx] = run;
            g_ROWCUR[idx] = run;
            run += g_DEG[idx] + 1;
        }
    }
    if (t == 1023) g_ROWPTR[NN] = sh[1023];
}

__global__ void k_scatter(const int* __restrict__ esrc, const int* __restrict__ edst) {
    int e = blockIdx.x * blockDim.x + threadIdx.x;
    if (e >= ETOT) return;
    int s, d;
    if (e < EE) { s = esrc[e]; d = edst[e]; } else { s = d = e - EE; }
    int pos = atomicAdd(&g_ROWCUR[d], 1);
    g_ESRT[pos] = s;
}

// ---------------- layer-1 aggregation over RAW features ----------------------
__global__ void k_agg1(const float* __restrict__ feats) {
    int lane = threadIdx.x & 31;
    int n = (blockIdx.x * blockDim.x + threadIdx.x) >> 5;
    if (n >= NN) return;
    int p0 = g_ROWPTR[n], p1 = g_ROWPTR[n + 1];
    float sd = (lane < NH) ? g_S1D[n * NH + lane] : 0.f;

    float aggx[NH];
#pragma unroll
    for (int h = 0; h < NH; h++) aggx[h] = 0.f;
    float denom = 0.f;

    int s_next = g_ESRT[p0];
    for (int k = p0; k < p1; k++) {
        int s = s_next;
        if (k + 1 < p1) s_next = g_ESRT[k + 1];
        float ex = 0.f;
        if (lane < NH)
            ex = __expf(leakyf(g_S1S[s * NH + lane] + sd));
        denom += ex;
        float xv = feats[s * FIN + lane];
#pragma unroll
        for (int h = 0; h < NH; h++) {
            float a = __shfl_sync(0xffffffffu, ex, h);
            aggx[h] = fmaf(a, xv, aggx[h]);
        }
    }
#pragma unroll
    for (int h = 0; h < NH; h++) {
        float d = fmaxf(__shfl_sync(0xffffffffu, denom, h), 1e-16f);
        g_AGG[(size_t)n * C1 + h * FIN + lane] = aggx[h] / d;
    }
}

// ---------------- block-diagonal GEMM1b: X1 = elu(AGG @ bd(W1) + b1) ---------
__global__ __launch_bounds__(256)
void k_gemm1b(const float* __restrict__ W1, const float* __restrict__ b1) {
    extern __shared__ float sm[];
    float* W1s = sm;                 // [c*32 + k] transposed
    float* As  = sm + C1 * FIN;      // [r*320 + c]
    int tid = threadIdx.x;
    int row0 = blockIdx.x * 64;

    for (int idx = tid; idx < C1 * FIN; idx += 256) {
        int c = idx >> 5, k = idx & 31;
        W1s[idx] = W1[k * C1 + c];
    }
    for (int f = tid; f < 64 * (C1 / 4); f += 256) {
        int r = f / 80, c4 = (f % 80) * 4;
        float4 v = {0.f, 0.f, 0.f, 0.f};
        if (row0 + r < NN)
            v = *reinterpret_cast<const float4*>(g_AGG + (size_t)(row0 + r) * C1 + c4);
        *reinterpret_cast<float4*>(&As[r * C1 + c4]) = v;
    }
    __syncthreads();

    int ty = tid >> 5, tx = tid & 31;
    float acc[8][NH];
#pragma unroll
    for (int i = 0; i < 8; i++)
#pragma unroll
        for (int h = 0; h < NH; h++) acc[i][h] = b1[h * FIN + tx];

    for (int k4 = 0; k4 < FIN; k4 += 4) {
        float4 w[NH];
#pragma unroll
        for (int h = 0; h < NH; h++)
            w[h] = *reinterpret_cast<const float4*>(&W1s[(h * FIN + tx) * FIN + k4]);
#pragma unroll
        for (int i = 0; i < 8; i++) {
            int r = ty * 8 + i;
#pragma unroll
            for (int h = 0; h < NH; h++) {
                float4 a = *reinterpret_cast<const float4*>(&As[r * C1 + h * FIN + k4]);
                acc[i][h] += a.x * w[h].x + a.y * w[h].y + a.z * w[h].z + a.w * w[h].w;
            }
        }
    }

#pragma unroll
    for (int i = 0; i < 8; i++) {
        int r = row0 + ty * 8 + i;
        if (r >= NN) continue;
#pragma unroll
        for (int h = 0; h < NH; h++)
            g_X1[(size_t)r * C1 + h * FIN + tx] = eluf(acc[i][h]);
    }
}

// ---------------- layer-2 scores ----------------------------------------------
__global__ void k_s2(const float* __restrict__ a2s, const float* __restrict__ a2d) {
    int lane = threadIdx.x & 31;
    int n = (blockIdx.x * blockDim.x + threadIdx.x) >> 5;
    if (n >= NN) return;
    const float* x = g_XW2 + (size_t)n * DOUT;
    float vs = 0.f, vd = 0.f;
#pragma unroll
    for (int j = 0; j < 4; j++) {
        float xv = x[j * 32 + lane];
        vs += xv * a2s[j * 32 + lane];
        vd += xv * a2d[j * 32 + lane];
    }
#pragma unroll
    for (int o = 16; o > 0; o >>= 1) {
        vs += __shfl_down_sync(0xffffffffu, vs, o);
        vd += __shfl_down_sync(0xffffffffu, vd, o);
    }
    if (lane == 0) { g_S2S[n] = vs; g_S2D[n] = vd; }
}

// ---------------- layer-2 aggregation + fused max-pool (single pass) ---------
__global__ void k_agg2(const float* __restrict__ b2) {
    int lane = threadIdx.x & 31;
    int n = (blockIdx.x * blockDim.x + threadIdx.x) >> 5;
    if (n >= NN) return;
    int p0 = g_ROWPTR[n], p1 = g_ROWPTR[n + 1];
    float sd = g_S2D[n];

    float4 acc = {0,0,0,0};
    float denom = 0.f;
    int s_next = g_ESRT[p0];
    for (int k = p0; k < p1; k++) {
        int s = s_next;
        if (k + 1 < p1) s_next = g_ESRT[k + 1];
        float ex = __expf(leakyf(g_S2S[s] + sd));
        denom += ex;
        float4 v = reinterpret_cast<const float4*>(g_XW2 + (size_t)s * DOUT)[lane];
        acc.x = fmaf(ex, v.x, acc.x); acc.y = fmaf(ex, v.y, acc.y);
        acc.z = fmaf(ex, v.z, acc.z); acc.w = fmaf(ex, v.w, acc.w);
    }
    float dn = fmaxf(denom, 1e-16f);
    float4 b = reinterpret_cast<const float4*>(b2)[lane];
    float4 o;
    o.x = fmaxf(acc.x / dn + b.x, 0.f);
    o.y = fmaxf(acc.y / dn + b.y, 0.f);
    o.z = fmaxf(acc.z / dn + b.z, 0.f);
    o.w = fmaxf(acc.w / dn + b.w, 0.f);
    reinterpret_cast<float4*>(g_X2E + (size_t)n * DOUT)[lane] = o;

    int grow = NN + n / PERN;
    int* pm = reinterpret_cast<int*>(g_X2E + (size_t)grow * DOUT + lane * 4);
    atomicMax(pm + 0, __float_as_int(o.x));
    atomicMax(pm + 1, __float_as_int(o.y));
    atomicMax(pm + 2, __float_as_int(o.z));
    atomicMax(pm + 3, __float_as_int(o.w));
}

// ============================================================================
extern "C" void kernel_launch(void* const* d_in, const int* in_sizes, int n_in,
                              void* d_out, int out_size) {
    const float* feats = (const float*)d_in[0];
    const int*   ei    = (const int*)d_in[1];
    const int*   esrc  = ei;
    const int*   edst  = ei + EE;
    const float* W1  = (const float*)d_in[4];
    const float* a1s = (const float*)d_in[5];
    const float* a1d = (const float*)d_in[6];
    const float* b1  = (const float*)d_in[7];
    const float* W2  = (const float*)d_in[8];
    const float* a2s = (const float*)d_in[9];
    const float* a2d = (const float*)d_in[10];
    const float* b2  = (const float*)d_in[11];
    const float* fcw = (const float*)d_in[12];
    const float* fcb = (const float*)d_in[13];
    float* out = (float*)d_out;

    void *pX1, *pXW2, *pX2E, *pDEG;
    cudaGetSymbolAddress(&pX1,   g_X1);
    cudaGetSymbolAddress(&pXW2,  g_XW2);
    cudaGetSymbolAddress(&pX2E,  g_X2E);
    cudaGetSymbolAddress(&pDEG,  g_DEG);

    const int SMEM1B = (C1 * FIN + 64 * C1) * (int)sizeof(float);  // 122880
    cudaFuncSetAttribute(k_gemm1b, cudaFuncAttributeMaxDynamicSharedMemorySize, SMEM1B);

    const int WB = 256;
    int warpBlocks = (NN * 32 + WB - 1) / WB;

    cudaMemsetAsync(pDEG, 0, NN * sizeof(int));
    cudaMemsetAsync((float*)pX2E + (size_t)NN * DOUT, 0, BG * DOUT * sizeof(float));

    // CSR build
    k_count<<<(EE + 255) / 256, 256>>>(edst);
    k_prep<<<1, FIN * 20>>>(W1, a1s, a1d);
    k_scan<<<1, 1024>>>();
    k_scatter<<<(ETOT + 255) / 256, 256>>>(esrc, edst);

    // layer-1 scores + aggregation over raw features
    k_scores<<<(NN + 7) / 8, 256>>>(feats);
    k_agg1<<<warpBlocks, WB>>>(feats);

    // block-diagonal GEMM1b: X1 = elu(AGG @ bd(W1) + b1)
    k_gemm1b<<<(NN + 63) / 64, 256, SMEM1B>>>(W1, b1);

    // GEMM2: [20000,320] @ [320,128] (TF32 3x)
    dim3 g2((NN + 127) / 128, 1);
    k_tgemm<0><<<g2, 256>>>((const float*)pX1, W2, nullptr,
                            (float*)pXW2, NN, DOUT, C1);

    k_s2<<<warpBlocks, WB>>>(a2s, a2d);
    k_agg2<<<warpBlocks, WB>>>(b2);

    // single FC GEMM over node rows + pooled rows -> entire output
    dim3 g3((NN + BG + 127) / 128, 1);
    k_tgemm<1><<<g3, 256>>>((const float*)pX2E, fcw, fcb, out,
                            NN + BG, DOUT, DOUT);
}

// round 7
// speedup vs baseline: 1.2927x; 1.2927x over previous
#include <cuda_runtime.h>
#include <cuda_fp16.h>

#define NN    20000
#define BG    100
#define PERN  200
#define EE    320000
#define ETOT  340000
#define FIN   32
#define NH    10
#define C1    320
#define C1E   340
#define DOUT  128
#define NEG_SLOPE 0.2f

// ---------------- scratch ----------------------------------------------------
__device__ __half g_XW1H[NN * C1];          // layer-1 transformed feats, fp16
__device__ float  g_S1S [NN * NH];
__device__ float  g_S1D [NN * NH];
__device__ float  g_X1  [NN * C1];          // layer-1 output after elu (fp32)
__device__ __half g_XW2H[NN * DOUT];        // layer-2 transformed feats, fp16
__device__ float  g_S2S [NN];
__device__ float  g_S2D [NN];
__device__ float  g_X2E [(NN + BG) * DOUT]; // node rows + pooled rows
__device__ float  g_B1E [FIN * C1E];        // extended B for GEMM1
__device__ float  g_Q2S [C1];               // W2 @ a2_src
__device__ float  g_Q2D [C1];               // W2 @ a2_dst
__device__ int    g_DEG[NN];
__device__ int    g_ROWPTR[NN + 1];
__device__ int    g_ROWCUR[NN];
__device__ int    g_ESRT[ETOT];

__device__ __forceinline__ float leakyf(float x) { return x > 0.f ? x : NEG_SLOPE * x; }
__device__ __forceinline__ float eluf(float x)   { return x > 0.f ? x : __expf(x) - 1.f; }

__device__ __forceinline__ unsigned f2tf(float x) {
    unsigned r;
    asm("cvt.rna.tf32.f32 %0, %1;" : "=r"(r) : "f"(x));
    return r;
}
__device__ __forceinline__ void mma8(float* d, const unsigned* a, const unsigned* b) {
    asm volatile(
        "mma.sync.aligned.m16n8k8.row.col.f32.tf32.tf32.f32 "
        "{%0,%1,%2,%3}, {%4,%5,%6,%7}, {%8,%9}, {%0,%1,%2,%3};\n"
        : "+f"(d[0]), "+f"(d[1]), "+f"(d[2]), "+f"(d[3])
        : "r"(a[0]), "r"(a[1]), "r"(a[2]), "r"(a[3]), "r"(b[0]), "r"(b[1]));
}

// MODE2 store: GEMM1 epilogue -> fp16 features + fp32 score cols
__device__ __forceinline__ void st_m2(int r, int c, float2 v) {
    if (c < C1) {
        *reinterpret_cast<__half2*>(g_XW1H + (size_t)r * C1 + c) =
            __floats2half2_rn(v.x, v.y);
    } else {
        int sc = c - C1;          // even; pairs never straddle the 10-boundary
        if (sc < NH) {
            g_S1S[r * NH + sc]     = v.x;
            g_S1S[r * NH + sc + 1] = v.y;
        } else if (sc < 20) {
            g_S1D[r * NH + sc - NH]     = v.x;
            g_S1D[r * NH + sc - NH + 1] = v.y;
        }
    }
}

// ---------------- TF32 tensor-core GEMM (3xTF32) ------------------------------
// MODE: 1 = bias+relu fp32 out, 2 = GEMM1 special (fp16 feats + fp32 scores),
//       4 = fp16 out (GEMM2)
template <int MODE>
__global__ __launch_bounds__(256)
void k_tgemm(const float* __restrict__ A, const float* __restrict__ B,
             const float* __restrict__ bias, float* __restrict__ C,
             int M, int N, int K) {
    __shared__ float As[16][136];
    __shared__ float Bs[16][136];
    const int tid  = threadIdx.x;
    const int lane = tid & 31;
    const int wid  = tid >> 5;
    const int qr   = lane >> 2;
    const int qc   = lane & 3;
    const int wm   = (wid & 3) * 32;
    const int wn   = (wid >> 2) * 64;
    const int row0 = blockIdx.x * 128;
    const int col0 = blockIdx.y * 128;

    float acc[2][8][4];
#pragma unroll
    for (int mf = 0; mf < 2; mf++)
#pragma unroll
        for (int nf = 0; nf < 8; nf++)
#pragma unroll
            for (int i = 0; i < 4; i++) acc[mf][nf][i] = 0.f;

    for (int k0 = 0; k0 < K; k0 += 16) {
#pragma unroll
        for (int i = 0; i < 2; i++) {
            int f = tid + i * 256;
            int r = f >> 2, c4 = (f & 3) * 4;
            float4 v = {0.f, 0.f, 0.f, 0.f};
            if (row0 + r < M)
                v = *reinterpret_cast<const float4*>(A + (size_t)(row0 + r) * K + k0 + c4);
            As[c4 + 0][r] = v.x; As[c4 + 1][r] = v.y;
            As[c4 + 2][r] = v.z; As[c4 + 3][r] = v.w;
        }
#pragma unroll
        for (int i = 0; i < 2; i++) {
            int f = tid + i * 256;
            int kk = f >> 5, c4 = (f & 31) * 4;
            float4 v = {0.f, 0.f, 0.f, 0.f};
            const float* src = B + (size_t)(k0 + kk) * N + col0 + c4;
            if (col0 + c4 + 3 < N) {
                v = *reinterpret_cast<const float4*>(src);
            } else {
                if (col0 + c4 + 0 < N) v.x = src[0];
                if (col0 + c4 + 1 < N) v.y = src[1];
                if (col0 + c4 + 2 < N) v.z = src[2];
                if (col0 + c4 + 3 < N) v.w = src[3];
            }
            *reinterpret_cast<float4*>(&Bs[kk][c4]) = v;
        }
        __syncthreads();

#pragma unroll
        for (int ks = 0; ks < 16; ks += 8) {
            unsigned ah[2][4], al[2][4], bh[8][2], bl[8][2];
#pragma unroll
            for (int mf = 0; mf < 2; mf++) {
                int mb = wm + mf * 16 + qr;
                float x0 = As[ks + qc][mb];
                float x1 = As[ks + qc][mb + 8];
                float x2 = As[ks + qc + 4][mb];
                float x3 = As[ks + qc + 4][mb + 8];
                ah[mf][0] = f2tf(x0); al[mf][0] = f2tf(x0 - __uint_as_float(ah[mf][0]));
                ah[mf][1] = f2tf(x1); al[mf][1] = f2tf(x1 - __uint_as_float(ah[mf][1]));
                ah[mf][2] = f2tf(x2); al[mf][2] = f2tf(x2 - __uint_as_float(ah[mf][2]));
                ah[mf][3] = f2tf(x3); al[mf][3] = f2tf(x3 - __uint_as_float(ah[mf][3]));
            }
#pragma unroll
            for (int nf = 0; nf < 8; nf++) {
                int nb = wn + nf * 8 + qr;
                float y0 = Bs[ks + qc][nb];
                float y1 = Bs[ks + qc + 4][nb];
                bh[nf][0] = f2tf(y0); bl[nf][0] = f2tf(y0 - __uint_as_float(bh[nf][0]));
                bh[nf][1] = f2tf(y1); bl[nf][1] = f2tf(y1 - __uint_as_float(bh[nf][1]));
            }
#pragma unroll
            for (int mf = 0; mf < 2; mf++)
#pragma unroll
                for (int nf = 0; nf < 8; nf++) {
                    mma8(acc[mf][nf], ah[mf], bh[nf]);
                    mma8(acc[mf][nf], al[mf], bh[nf]);
                    mma8(acc[mf][nf], ah[mf], bl[nf]);
                }
        }
        __syncthreads();
    }

#pragma unroll
    for (int mf = 0; mf < 2; mf++) {
        int r0 = row0 + wm + mf * 16 + qr;
#pragma unroll
        for (int nf = 0; nf < 8; nf++) {
            int c = col0 + wn + nf * 8 + 2 * qc;
            float2 v0 = {acc[mf][nf][0], acc[mf][nf][1]};
            float2 v1 = {acc[mf][nf][2], acc[mf][nf][3]};
            if (MODE == 1) {
                float bc0 = bias[c], bc1 = bias[c + 1];
                v0.x = fmaxf(v0.x + bc0, 0.f); v0.y = fmaxf(v0.y + bc1, 0.f);
                v1.x = fmaxf(v1.x + bc0, 0.f); v1.y = fmaxf(v1.y + bc1, 0.f);
                if (r0 < M && c + 1 < N)
                    *reinterpret_cast<float2*>(C + (size_t)r0 * N + c) = v0;
                if (r0 + 8 < M && c + 1 < N)
                    *reinterpret_cast<float2*>(C + (size_t)(r0 + 8) * N + c) = v1;
            } else if (MODE == 2) {
                if (r0 < M)     st_m2(r0, c, v0);
                if (r0 + 8 < M) st_m2(r0 + 8, c, v1);
            } else if (MODE == 4) {
                if (r0 < M)
                    *reinterpret_cast<__half2*>(g_XW2H + (size_t)r0 * DOUT + c) =
                        __floats2half2_rn(v0.x, v0.y);
                if (r0 + 8 < M)
                    *reinterpret_cast<__half2*>(g_XW2H + (size_t)(r0 + 8) * DOUT + c) =
                        __floats2half2_rn(v1.x, v1.y);
            }
        }
    }
}

// ---------------- build extended B1 [32 x 340] -------------------------------
__global__ void k_bext1(const float* __restrict__ W1, const float* __restrict__ a1s,
                        const float* __restrict__ a1d) {
    int k = blockIdx.x;
    int j = threadIdx.x;
    if (j >= C1E) return;
    float v;
    if (j < C1) {
        v = W1[k * C1 + j];
    } else if (j < C1 + NH) {
        int h = j - C1;
        float s = 0.f;
        for (int f = 0; f < FIN; f++)
            s += W1[k * C1 + h * FIN + f] * a1s[h * FIN + f];
        v = s;
    } else {
        int h = j - C1 - NH;
        float s = 0.f;
        for (int f = 0; f < FIN; f++)
            s += W1[k * C1 + h * FIN + f] * a1d[h * FIN + f];
        v = s;
    }
    g_B1E[k * C1E + j] = v;
}

// ---------------- Q2 = W2 @ a2_{src,dst}  [320]x2 ----------------------------
__global__ void k_q2(const float* __restrict__ W2, const float* __restrict__ a2s,
                     const float* __restrict__ a2d) {
    int k = threadIdx.x;
    if (k >= C1) return;
    float s = 0.f, d = 0.f;
    for (int f = 0; f < DOUT; f++) {
        float w = W2[k * DOUT + f];
        s += w * a2s[f];
        d += w * a2d[f];
    }
    g_Q2S[k] = s;
    g_Q2D[k] = d;
}

// ---------------- CSR build ---------------------------------------------------
__global__ void k_count(const int* __restrict__ edst) {
    int e = blockIdx.x * blockDim.x + threadIdx.x;
    if (e < EE) atomicAdd(&g_DEG[edst[e]], 1);
}

__global__ void k_scan() {
    const int CH = 20;
    __shared__ int sh[1024];
    int t = threadIdx.x;
    int start = t * CH;
    int s = 0;
    for (int i = 0; i < CH; i++) {
        int idx = start + i;
        if (idx < NN) s += g_DEG[idx] + 1;
    }
    sh[t] = s;
    __syncthreads();
    for (int off = 1; off < 1024; off <<= 1) {
        int v = (t >= off) ? sh[t - off] : 0;
        __syncthreads();
        sh[t] += v;
        __syncthreads();
    }
    int run = (t > 0) ? sh[t - 1] : 0;
    for (int i = 0; i < CH; i++) {
        int idx = start + i;
        if (idx < NN) {
            g_ROWPTR[idx] = run;
            g_ROWCUR[idx] = run;
            run += g_DEG[idx] + 1;
        }
    }
    if (t == 1023) g_ROWPTR[NN] = sh[1023];
}

__global__ void k_scatter(const int* __restrict__ esrc, const int* __restrict__ edst) {
    int e = blockIdx.x * blockDim.x + threadIdx.x;
    if (e >= ETOT) return;
    int s, d;
    if (e < EE) { s = esrc[e]; d = edst[e]; } else { s = d = e - EE; }
    int pos = atomicAdd(&g_ROWCUR[d], 1);
    g_ESRT[pos] = s;
}

// ---------------- layer-1 aggregation over fp16 xw rows ----------------------
// warp per node; lane owns half2 words {lane+32j}, j=0..4 (160 words = 320 cols).
// word w -> head w>>4. Single pass (no max). Fuses bias+elu+X1 store AND the
// layer-2 score projections s2 = X1 @ Q2.
__global__ void k_agg1(const float* __restrict__ b1) {
    int lane = threadIdx.x & 31;
    int n = (blockIdx.x * blockDim.x + threadIdx.x) >> 5;
    if (n >= NN) return;
    int p0 = g_ROWPTR[n], p1 = g_ROWPTR[n + 1];
    float sd = (lane < NH) ? g_S1D[n * NH + lane] : 0.f;
    int hbase = lane >> 4;   // 0 or 1

    float2 acc[5];
#pragma unroll
    for (int j = 0; j < 5; j++) acc[j] = make_float2(0.f, 0.f);
    float denom = 0.f;

    int s_next = g_ESRT[p0];
    for (int k = p0; k < p1; k++) {
        int s = s_next;
        if (k + 1 < p1) s_next = g_ESRT[k + 1];
        float ex = (lane < NH) ? __expf(leakyf(g_S1S[s * NH + lane] + sd)) : 0.f;
        denom += ex;
        const __half2* row = reinterpret_cast<const __half2*>(g_XW1H + (size_t)s * C1);
#pragma unroll
        for (int j = 0; j < 5; j++) {
            float a = __shfl_sync(0xffffffffu, ex, hbase + 2 * j);
            float2 v = __half22float2(row[lane + 32 * j]);
            acc[j].x = fmaf(a, v.x, acc[j].x);
            acc[j].y = fmaf(a, v.y, acc[j].y);
        }
    }

    float vs = 0.f, vd = 0.f;
#pragma unroll
    for (int j = 0; j < 5; j++) {
        float d = fmaxf(__shfl_sync(0xffffffffu, denom, hbase + 2 * j), 1e-16f);
        int w = lane + 32 * j;
        float2 b = reinterpret_cast<const float2*>(b1)[w];
        float ox = eluf(acc[j].x / d + b.x);
        float oy = eluf(acc[j].y / d + b.y);
        *reinterpret_cast<float2*>(g_X1 + (size_t)n * C1 + 2 * w) = make_float2(ox, oy);
        vs += ox * g_Q2S[2 * w] + oy * g_Q2S[2 * w + 1];
        vd += ox * g_Q2D[2 * w] + oy * g_Q2D[2 * w + 1];
    }
#pragma unroll
    for (int o = 16; o > 0; o >>= 1) {
        vs += __shfl_down_sync(0xffffffffu, vs, o);
        vd += __shfl_down_sync(0xffffffffu, vd, o);
    }
    if (lane == 0) { g_S2S[n] = vs; g_S2D[n] = vd; }
}

// ---------------- layer-2 aggregation (fp16 gather) + fused max-pool ---------
__global__ void k_agg2(const float* __restrict__ b2) {
    int lane = threadIdx.x & 31;
    int n = (blockIdx.x * blockDim.x + threadIdx.x) >> 5;
    if (n >= NN) return;
    int p0 = g_ROWPTR[n], p1 = g_ROWPTR[n + 1];
    float sd = g_S2D[n];

    float2 acc0 = {0.f, 0.f}, acc1 = {0.f, 0.f};
    float denom = 0.f;
    int s_next = g_ESRT[p0];
    for (int k = p0; k < p1; k++) {
        int s = s_next;
        if (k + 1 < p1) s_next = g_ESRT[k + 1];
        float ex = __expf(leakyf(g_S2S[s] + sd));
        denom += ex;
        const __half2* row = reinterpret_cast<const __half2*>(g_XW2H + (size_t)s * DOUT);
        float2 v0 = __half22float2(row[lane]);
        float2 v1 = __half22float2(row[lane + 32]);
        acc0.x = fmaf(ex, v0.x, acc0.x); acc0.y = fmaf(ex, v0.y, acc0.y);
        acc1.x = fmaf(ex, v1.x, acc1.x); acc1.y = fmaf(ex, v1.y, acc1.y);
    }
    float dn = fmaxf(denom, 1e-16f);
    float2 b0 = reinterpret_cast<const float2*>(b2)[lane];
    float2 b1v = reinterpret_cast<const float2*>(b2)[lane + 32];
    float2 o0, o1;
    o0.x = fmaxf(acc0.x / dn + b0.x, 0.f);
    o0.y = fmaxf(acc0.y / dn + b0.y, 0.f);
    o1.x = fmaxf(acc1.x / dn + b1v.x, 0.f);
    o1.y = fmaxf(acc1.y / dn + b1v.y, 0.f);
    *reinterpret_cast<float2*>(g_X2E + (size_t)n * DOUT + 2 * lane) = o0;
    *reinterpret_cast<float2*>(g_X2E + (size_t)n * DOUT + 64 + 2 * lane) = o1;

    int grow = NN + n / PERN;
    int* pm0 = reinterpret_cast<int*>(g_X2E + (size_t)grow * DOUT + 2 * lane);
    int* pm1 = reinterpret_cast<int*>(g_X2E + (size_t)grow * DOUT + 64 + 2 * lane);
    atomicMax(pm0 + 0, __float_as_int(o0.x));
    atomicMax(pm0 + 1, __float_as_int(o0.y));
    atomicMax(pm1 + 0, __float_as_int(o1.x));
    atomicMax(pm1 + 1, __float_as_int(o1.y));
}

// ============================================================================
extern "C" void kernel_launch(void* const* d_in, const int* in_sizes, int n_in,
                              void* d_out, int out_size) {
    const float* feats = (const float*)d_in[0];
    const int*   ei    = (const int*)d_in[1];
    const int*   esrc  = ei;
    const int*   edst  = ei + EE;
    const float* W1  = (const float*)d_in[4];
    const float* a1s = (const float*)d_in[5];
    const float* a1d = (const float*)d_in[6];
    const float* b1  = (const float*)d_in[7];
    const float* W2  = (const float*)d_in[8];
    const float* a2s = (const float*)d_in[9];
    const float* a2d = (const float*)d_in[10];
    const float* b2  = (const float*)d_in[11];
    const float* fcw = (const float*)d_in[12];
    const float* fcb = (const float*)d_in[13];
    float* out = (float*)d_out;

    void *pX1, *pX2E, *pB1E, *pDEG;
    cudaGetSymbolAddress(&pX1,  g_X1);
    cudaGetSymbolAddress(&pX2E, g_X2E);
    cudaGetSymbolAddress(&pB1E, g_B1E);
    cudaGetSymbolAddress(&pDEG, g_DEG);

    const int WB = 256;
    int warpBlocks = (NN * 32 + WB - 1) / WB;

    cudaMemsetAsync(pDEG, 0, NN * sizeof(int));
    cudaMemsetAsync((float*)pX2E + (size_t)NN * DOUT, 0, BG * DOUT * sizeof(float));

    // CSR build + weight preprocessing
    k_count<<<(EE + 255) / 256, 256>>>(edst);
    k_bext1<<<FIN, 352>>>(W1, a1s, a1d);
    k_q2<<<1, C1>>>(W2, a2s, a2d);
    k_scan<<<1, 1024>>>();
    k_scatter<<<(ETOT + 255) / 256, 256>>>(esrc, edst);

    // GEMM1: [20000,32] @ [32,340] -> fp16 feats + fp32 scores
    dim3 g1((NN + 127) / 128, (C1E + 127) / 128);
    k_tgemm<2><<<g1, 256>>>(feats, (const float*)pB1E, nullptr, nullptr,
                            NN, C1E, FIN);

    // layer-1 aggregation (+ bias + elu + X1 store + layer-2 scores)
    k_agg1<<<warpBlocks, WB>>>(b1);

    // GEMM2: [20000,320] @ [320,128] -> fp16 XW2H
    dim3 g2((NN + 127) / 128, 1);
    k_tgemm<4><<<g2, 256>>>((const float*)pX1, W2, nullptr, nullptr,
                            NN, DOUT, C1);

    // layer-2 aggregation + pool
    k_agg2<<<warpBlocks, WB>>>(b2);

    // FC over node rows + pooled rows -> entire output
    dim3 g3((NN + BG + 127) / 128, 1);
    k_tgemm<1><<<g3, 256>>>((const float*)pX2E, fcw, fcb, out,
                            NN + BG, DOUT, DOUT);
}

// round 8
// speedup vs baseline: 1.4730x; 1.1395x over previous
#include <cuda_runtime.h>
#include <cuda_fp16.h>
#include <cuda_bf16.h>

#define NN    20000
#define BG    100
#define PERN  200
#define EE    320000
#define ETOT  340000
#define FIN   32
#define NH    10
#define C1    320
#define C1E   340
#define DOUT  128
#define NEG_SLOPE 0.2f

// ---------------- scratch ----------------------------------------------------
__device__ __half g_XW1H[NN * C1];          // layer-1 transformed feats, fp16
__device__ float  g_S1S [NN * NH];
__device__ float  g_S1D [NN * NH];
__device__ float  g_X1  [NN * C1];          // layer-1 output after elu (fp32)
__device__ __half g_XW2H[NN * DOUT];        // layer-2 transformed feats, fp16
__device__ float  g_S2S [NN];
__device__ float  g_S2D [NN];
__device__ float  g_X2E [(NN + BG) * DOUT]; // node rows + pooled rows
__device__ float  g_B1E [FIN * C1E];        // extended B for GEMM1
__device__ float  g_Q2S [C1];               // W2 @ a2_src
__device__ float  g_Q2D [C1];               // W2 @ a2_dst
__device__ int    g_DEG[NN];
__device__ int    g_ROWPTR[NN + 1];
__device__ int    g_ROWCUR[NN];
__device__ int    g_ESRT[ETOT];
__device__ int    g_BSUM[32];
__device__ int    g_BOFF[32];

__device__ __forceinline__ float leakyf(float x) { return x > 0.f ? x : NEG_SLOPE * x; }
__device__ __forceinline__ float eluf(float x)   { return x > 0.f ? x : __expf(x) - 1.f; }

// bf16 hi/lo split of two floats, packed for mma operands
__device__ __forceinline__ void bfsplit2(float x0, float x1, unsigned& h, unsigned& l) {
    __nv_bfloat162 hv = __floats2bfloat162_rn(x0, x1);
    float r0 = x0 - __bfloat162float(hv.x);
    float r1 = x1 - __bfloat162float(hv.y);
    __nv_bfloat162 lv = __floats2bfloat162_rn(r0, r1);
    h = *reinterpret_cast<unsigned*>(&hv);
    l = *reinterpret_cast<unsigned*>(&lv);
}

__device__ __forceinline__ void mma16(float* d, const unsigned* a, const unsigned* b) {
    asm volatile(
        "mma.sync.aligned.m16n8k16.row.col.f32.bf16.bf16.f32 "
        "{%0,%1,%2,%3}, {%4,%5,%6,%7}, {%8,%9}, {%0,%1,%2,%3};\n"
        : "+f"(d[0]), "+f"(d[1]), "+f"(d[2]), "+f"(d[3])
        : "r"(a[0]), "r"(a[1]), "r"(a[2]), "r"(a[3]), "r"(b[0]), "r"(b[1]));
}

// MODE2 store: GEMM1 epilogue -> fp16 features + fp32 score cols
__device__ __forceinline__ void st_m2(int r, int c, float2 v) {
    if (c < C1) {
        *reinterpret_cast<__half2*>(g_XW1H + (size_t)r * C1 + c) =
            __floats2half2_rn(v.x, v.y);
    } else {
        int sc = c - C1;          // even; pairs never straddle the 10-boundary
        if (sc < NH) {
            g_S1S[r * NH + sc]     = v.x;
            g_S1S[r * NH + sc + 1] = v.y;
        } else if (sc < 20) {
            g_S1D[r * NH + sc - NH]     = v.x;
            g_S1D[r * NH + sc - NH + 1] = v.y;
        }
    }
}

// ---------------- bf16x3 tensor-core GEMM (fp32-accurate) ---------------------
// 128x128 tile, BK=16 (one k16 mma chunk per tile), 256 threads.
// MODE: 1 = bias+relu fp32 out, 2 = GEMM1 special, 4 = fp16 out (GEMM2)
template <int MODE>
__global__ __launch_bounds__(256)
void k_tgemm(const float* __restrict__ A, const float* __restrict__ B,
             const float* __restrict__ bias, float* __restrict__ C,
             int M, int N, int K) {
    __shared__ float As[16][136];
    __shared__ float Bs[16][136];
    const int tid  = threadIdx.x;
    const int lane = tid & 31;
    const int wid  = tid >> 5;
    const int qr   = lane >> 2;
    const int qc   = lane & 3;
    const int wm   = (wid & 3) * 32;
    const int wn   = (wid >> 2) * 64;
    const int row0 = blockIdx.x * 128;
    const int col0 = blockIdx.y * 128;

    float acc[2][8][4];
#pragma unroll
    for (int mf = 0; mf < 2; mf++)
#pragma unroll
        for (int nf = 0; nf < 8; nf++)
#pragma unroll
            for (int i = 0; i < 4; i++) acc[mf][nf][i] = 0.f;

    for (int k0 = 0; k0 < K; k0 += 16) {
#pragma unroll
        for (int i = 0; i < 2; i++) {
            int f = tid + i * 256;
            int r = f >> 2, c4 = (f & 3) * 4;
            float4 v = {0.f, 0.f, 0.f, 0.f};
            if (row0 + r < M)
                v = *reinterpret_cast<const float4*>(A + (size_t)(row0 + r) * K + k0 + c4);
            As[c4 + 0][r] = v.x; As[c4 + 1][r] = v.y;
            As[c4 + 2][r] = v.z; As[c4 + 3][r] = v.w;
        }
#pragma unroll
        for (int i = 0; i < 2; i++) {
            int f = tid + i * 256;
            int kk = f >> 5, c4 = (f & 31) * 4;
            float4 v = {0.f, 0.f, 0.f, 0.f};
            const float* src = B + (size_t)(k0 + kk) * N + col0 + c4;
            if (col0 + c4 + 3 < N) {
                v = *reinterpret_cast<const float4*>(src);
            } else {
                if (col0 + c4 + 0 < N) v.x = src[0];
                if (col0 + c4 + 1 < N) v.y = src[1];
                if (col0 + c4 + 2 < N) v.z = src[2];
                if (col0 + c4 + 3 < N) v.w = src[3];
            }
            *reinterpret_cast<float4*>(&Bs[kk][c4]) = v;
        }
        __syncthreads();

        unsigned ah[2][4], al[2][4], bh[8][2], bl[8][2];
#pragma unroll
        for (int mf = 0; mf < 2; mf++) {
            int mb = wm + mf * 16 + qr;
            bfsplit2(As[2*qc][mb],     As[2*qc+1][mb],     ah[mf][0], al[mf][0]);
            bfsplit2(As[2*qc][mb+8],   As[2*qc+1][mb+8],   ah[mf][1], al[mf][1]);
            bfsplit2(As[2*qc+8][mb],   As[2*qc+9][mb],     ah[mf][2], al[mf][2]);
            bfsplit2(As[2*qc+8][mb+8], As[2*qc+9][mb+8],   ah[mf][3], al[mf][3]);
        }
#pragma unroll
        for (int nf = 0; nf < 8; nf++) {
            int nb = wn + nf * 8 + qr;
            bfsplit2(Bs[2*qc][nb],   Bs[2*qc+1][nb], bh[nf][0], bl[nf][0]);
            bfsplit2(Bs[2*qc+8][nb], Bs[2*qc+9][nb], bh[nf][1], bl[nf][1]);
        }
#pragma unroll
        for (int mf = 0; mf < 2; mf++)
#pragma unroll
            for (int nf = 0; nf < 8; nf++) {
                mma16(acc[mf][nf], ah[mf], bh[nf]);
                mma16(acc[mf][nf], al[mf], bh[nf]);
                mma16(acc[mf][nf], ah[mf], bl[nf]);
            }
        __syncthreads();
    }

#pragma unroll
    for (int mf = 0; mf < 2; mf++) {
        int r0 = row0 + wm + mf * 16 + qr;
#pragma unroll
        for (int nf = 0; nf < 8; nf++) {
            int c = col0 + wn + nf * 8 + 2 * qc;
            float2 v0 = {acc[mf][nf][0], acc[mf][nf][1]};
            float2 v1 = {acc[mf][nf][2], acc[mf][nf][3]};
            if (MODE == 1) {
                float bc0 = bias[c], bc1 = bias[c + 1];
                v0.x = fmaxf(v0.x + bc0, 0.f); v0.y = fmaxf(v0.y + bc1, 0.f);
                v1.x = fmaxf(v1.x + bc0, 0.f); v1.y = fmaxf(v1.y + bc1, 0.f);
                if (r0 < M && c + 1 < N)
                    *reinterpret_cast<float2*>(C + (size_t)r0 * N + c) = v0;
                if (r0 + 8 < M && c + 1 < N)
                    *reinterpret_cast<float2*>(C + (size_t)(r0 + 8) * N + c) = v1;
            } else if (MODE == 2) {
                if (r0 < M)     st_m2(r0, c, v0);
                if (r0 + 8 < M) st_m2(r0 + 8, c, v1);
            } else if (MODE == 4) {
                if (r0 < M)
                    *reinterpret_cast<__half2*>(g_XW2H + (size_t)r0 * DOUT + c) =
                        __floats2half2_rn(v0.x, v0.y);
                if (r0 + 8 < M)
                    *reinterpret_cast<__half2*>(g_XW2H + (size_t)(r0 + 8) * DOUT + c) =
                        __floats2half2_rn(v1.x, v1.y);
            }
        }
    }
}

// ---------------- build extended B1 [32 x 340] -------------------------------
__global__ void k_bext1(const float* __restrict__ W1, const float* __restrict__ a1s,
                        const float* __restrict__ a1d) {
    int k = blockIdx.x;
    int j = threadIdx.x;
    if (j >= C1E) return;
    float v;
    if (j < C1) {
        v = W1[k * C1 + j];
    } else if (j < C1 + NH) {
        int h = j - C1;
        float s = 0.f;
        for (int f = 0; f < FIN; f++)
            s += W1[k * C1 + h * FIN + f] * a1s[h * FIN + f];
        v = s;
    } else {
        int h = j - C1 - NH;
        float s = 0.f;
        for (int f = 0; f < FIN; f++)
            s += W1[k * C1 + h * FIN + f] * a1d[h * FIN + f];
        v = s;
    }
    g_B1E[k * C1E + j] = v;
}

// ---------------- Q2 = W2 @ a2_{src,dst}, warp-per-k --------------------------
__global__ void k_q2(const float* __restrict__ W2, const float* __restrict__ a2s,
                     const float* __restrict__ a2d) {
    int lane = threadIdx.x & 31;
    int k = (blockIdx.x * blockDim.x + threadIdx.x) >> 5;
    if (k >= C1) return;
    float s = 0.f, d = 0.f;
#pragma unroll
    for (int j = 0; j < 4; j++) {
        float w = W2[k * DOUT + j * 32 + lane];
        s += w * a2s[j * 32 + lane];
        d += w * a2d[j * 32 + lane];
    }
#pragma unroll
    for (int o = 16; o > 0; o >>= 1) {
        s += __shfl_down_sync(0xffffffffu, s, o);
        d += __shfl_down_sync(0xffffffffu, d, o);
    }
    if (lane == 0) { g_Q2S[k] = s; g_Q2D[k] = d; }
}

// ---------------- CSR build: count + 3-stage parallel scan + scatter ---------
__global__ void k_count(const int* __restrict__ edst) {
    int e = blockIdx.x * blockDim.x + threadIdx.x;
    if (e < EE) atomicAdd(&g_DEG[edst[e]], 1);
}

__global__ void k_scanA() {                    // 20 blocks x 1024
    __shared__ int sh[1024];
    int b = blockIdx.x, t = threadIdx.x;
    int n = b * 1024 + t;
    int v = (n < NN) ? g_DEG[n] + 1 : 0;       // +1 self-loop
    sh[t] = v;
    __syncthreads();
    for (int o = 1; o < 1024; o <<= 1) {
        int u = (t >= o) ? sh[t - o] : 0;
        __syncthreads();
        sh[t] += u;
        __syncthreads();
    }
    if (n < NN) g_ROWPTR[n] = sh[t] - v;       // block-local exclusive prefix
    if (t == 1023) g_BSUM[b] = sh[t];
}

__global__ void k_scanB() {                    // 1 block x 32
    int t = threadIdx.x;
    int v = (t < 20) ? g_BSUM[t] : 0;
    int orig = v;
#pragma unroll
    for (int o = 1; o < 32; o <<= 1) {
        int u = __shfl_up_sync(0xffffffffu, v, o);
        if (t >= o) v += u;
    }
    if (t < 20) g_BOFF[t] = v - orig;          // exclusive
}

__global__ void k_scanC() {                    // 20 blocks x 1024
    int b = blockIdx.x, t = threadIdx.x;
    int n = b * 1024 + t;
    if (n < NN) {
        int r = g_ROWPTR[n] + g_BOFF[b];
        g_ROWPTR[n] = r;
        g_ROWCUR[n] = r;
    }
    if (b == 0 && t == 0) g_ROWPTR[NN] = ETOT;
}

__global__ void k_scatter(const int* __restrict__ esrc, const int* __restrict__ edst) {
    int e = blockIdx.x * blockDim.x + threadIdx.x;
    if (e >= ETOT) return;
    int s, d;
    if (e < EE) { s = esrc[e]; d = edst[e]; } else { s = d = e - EE; }
    int pos = atomicAdd(&g_ROWCUR[d], 1);
    g_ESRT[pos] = s;
}

// ---------------- layer-1 aggregation over fp16 xw rows ----------------------
__global__ void k_agg1(const float* __restrict__ b1) {
    int lane = threadIdx.x & 31;
    int n = (blockIdx.x * blockDim.x + threadIdx.x) >> 5;
    if (n >= NN) return;
    int p0 = g_ROWPTR[n], p1 = g_ROWPTR[n + 1];
    float sd = (lane < NH) ? g_S1D[n * NH + lane] : 0.f;
    int hbase = lane >> 4;   // 0 or 1

    float2 acc[5];
#pragma unroll
    for (int j = 0; j < 5; j++) acc[j] = make_float2(0.f, 0.f);
    float denom = 0.f;

    int s_next = g_ESRT[p0];
    for (int k = p0; k < p1; k++) {
        int s = s_next;
        if (k + 1 < p1) s_next = g_ESRT[k + 1];
        float ex = (lane < NH) ? __expf(leakyf(g_S1S[s * NH + lane] + sd)) : 0.f;
        denom += ex;
        const __half2* row = reinterpret_cast<const __half2*>(g_XW1H + (size_t)s * C1);
#pragma unroll
        for (int j = 0; j < 5; j++) {
            float a = __shfl_sync(0xffffffffu, ex, hbase + 2 * j);
            float2 v = __half22float2(row[lane + 32 * j]);
            acc[j].x = fmaf(a, v.x, acc[j].x);
            acc[j].y = fmaf(a, v.y, acc[j].y);
        }
    }

    float vs = 0.f, vd = 0.f;
#pragma unroll
    for (int j = 0; j < 5; j++) {
        float d = fmaxf(__shfl_sync(0xffffffffu, denom, hbase + 2 * j), 1e-16f);
        int w = lane + 32 * j;
        float2 b = reinterpret_cast<const float2*>(b1)[w];
        float ox = eluf(acc[j].x / d + b.x);
        float oy = eluf(acc[j].y / d + b.y);
        *reinterpret_cast<float2*>(g_X1 + (size_t)n * C1 + 2 * w) = make_float2(ox, oy);
        vs += ox * g_Q2S[2 * w] + oy * g_Q2S[2 * w + 1];
        vd += ox * g_Q2D[2 * w] + oy * g_Q2D[2 * w + 1];
    }
#pragma unroll
    for (int o = 16; o > 0; o >>= 1) {
        vs += __shfl_down_sync(0xffffffffu, vs, o);
        vd += __shfl_down_sync(0xffffffffu, vd, o);
    }
    if (lane == 0) { g_S2S[n] = vs; g_S2D[n] = vd; }
}

// ---------------- layer-2 aggregation (fp16 gather) + fused max-pool ---------
__global__ void k_agg2(const float* __restrict__ b2) {
    int lane = threadIdx.x & 31;
    int n = (blockIdx.x * blockDim.x + threadIdx.x) >> 5;
    if (n >= NN) return;
    int p0 = g_ROWPTR[n], p1 = g_ROWPTR[n + 1];
    float sd = g_S2D[n];

    float2 acc0 = {0.f, 0.f}, acc1 = {0.f, 0.f};
    float denom = 0.f;
    int s_next = g_ESRT[p0];
    for (int k = p0; k < p1; k++) {
        int s = s_next;
        if (k + 1 < p1) s_next = g_ESRT[k + 1];
        float ex = __expf(leakyf(g_S2S[s] + sd));
        denom += ex;
        const __half2* row = reinterpret_cast<const __half2*>(g_XW2H + (size_t)s * DOUT);
        float2 v0 = __half22float2(row[lane]);
        float2 v1 = __half22float2(row[lane + 32]);
        acc0.x = fmaf(ex, v0.x, acc0.x); acc0.y = fmaf(ex, v0.y, acc0.y);
        acc1.x = fmaf(ex, v1.x, acc1.x); acc1.y = fmaf(ex, v1.y, acc1.y);
    }
    float dn = fmaxf(denom, 1e-16f);
    float2 b0 = reinterpret_cast<const float2*>(b2)[lane];
    float2 b1v = reinterpret_cast<const float2*>(b2)[lane + 32];
    float2 o0, o1;
    o0.x = fmaxf(acc0.x / dn + b0.x, 0.f);
    o0.y = fmaxf(acc0.y / dn + b0.y, 0.f);
    o1.x = fmaxf(acc1.x / dn + b1v.x, 0.f);
    o1.y = fmaxf(acc1.y / dn + b1v.y, 0.f);
    *reinterpret_cast<float2*>(g_X2E + (size_t)n * DOUT + 2 * lane) = o0;
    *reinterpret_cast<float2*>(g_X2E + (size_t)n * DOUT + 64 + 2 * lane) = o1;

    int grow = NN + n / PERN;
    int* pm0 = reinterpret_cast<int*>(g_X2E + (size_t)grow * DOUT + 2 * lane);
    int* pm1 = reinterpret_cast<int*>(g_X2E + (size_t)grow * DOUT + 64 + 2 * lane);
    atomicMax(pm0 + 0, __float_as_int(o0.x));
    atomicMax(pm0 + 1, __float_as_int(o0.y));
    atomicMax(pm1 + 0, __float_as_int(o1.x));
    atomicMax(pm1 + 1, __float_as_int(o1.y));
}

// ============================================================================
extern "C" void kernel_launch(void* const* d_in, const int* in_sizes, int n_in,
                              void* d_out, int out_size) {
    const float* feats = (const float*)d_in[0];
    const int*   ei    = (const int*)d_in[1];
    const int*   esrc  = ei;
    const int*   edst  = ei + EE;
    const float* W1  = (const float*)d_in[4];
    const float* a1s = (const float*)d_in[5];
    const float* a1d = (const float*)d_in[6];
    const float* b1  = (const float*)d_in[7];
    const float* W2  = (const float*)d_in[8];
    const float* a2s = (const float*)d_in[9];
    const float* a2d = (const float*)d_in[10];
    const float* b2  = (const float*)d_in[11];
    const float* fcw = (const float*)d_in[12];
    const float* fcb = (const float*)d_in[13];
    float* out = (float*)d_out;

    void *pX1, *pX2E, *pB1E, *pDEG;
    cudaGetSymbolAddress(&pX1,  g_X1);
    cudaGetSymbolAddress(&pX2E, g_X2E);
    cudaGetSymbolAddress(&pB1E, g_B1E);
    cudaGetSymbolAddress(&pDEG, g_DEG);

    const int WB = 256;
    int warpBlocks = (NN * 32 + WB - 1) / WB;

    cudaMemsetAsync(pDEG, 0, NN * sizeof(int));
    cudaMemsetAsync((float*)pX2E + (size_t)NN * DOUT, 0, BG * DOUT * sizeof(float));

    // CSR build + weight preprocessing
    k_count<<<(EE + 255) / 256, 256>>>(edst);
    k_bext1<<<FIN, 352>>>(W1, a1s, a1d);
    k_q2<<<(C1 * 32 + 255) / 256, 256>>>(W2, a2s, a2d);
    k_scanA<<<20, 1024>>>();
    k_scanB<<<1, 32>>>();
    k_scanC<<<20, 1024>>>();
    k_scatter<<<(ETOT + 255) / 256, 256>>>(esrc, edst);

    // GEMM1: [20000,32] @ [32,340] -> fp16 feats + fp32 scores
    dim3 g1((NN + 127) / 128, (C1E + 127) / 128);
    k_tgemm<2><<<g1, 256>>>(feats, (const float*)pB1E, nullptr, nullptr,
                            NN, C1E, FIN);

    // layer-1 aggregation (+ bias + elu + X1 store + layer-2 scores)
    k_agg1<<<warpBlocks, WB>>>(b1);

    // GEMM2: [20000,320] @ [320,128] -> fp16 XW2H
    dim3 g2((NN + 127) / 128, 1);
    k_tgemm<4><<<g2, 256>>>((const float*)pX1, W2, nullptr, nullptr,
                            NN, DOUT, C1);

    // layer-2 aggregation + pool
    k_agg2<<<warpBlocks, WB>>>(b2);

    // FC over node rows + pooled rows -> entire output
    dim3 g3((NN + BG + 127) / 128, 1);
    k_tgemm<1><<<g3, 256>>>((const float*)pX2E, fcw, fcb, out,
                            NN + BG, DOUT, DOUT);
}

// round 9
// speedup vs baseline: 1.9509x; 1.3244x over previous
#include <cuda_runtime.h>
#include <cuda_fp16.h>
#include <cuda_bf16.h>

#define NN    20000
#define BG    100
#define PERN  200
#define EE    320000
#define ETOT  340000
#define FIN   32
#define NH    10
#define C1    320
#define C1E   340
#define DOUT  128
#define NEG_SLOPE 0.2f

// ---------------- scratch ----------------------------------------------------
__device__ __half g_XW1H[NN * C1];          // layer-1 transformed feats, fp16
__device__ float  g_S1S [NN * NH];
__device__ float  g_S1D [NN * NH];
__device__ __half g_X1H [NN * C1];          // layer-1 output after elu, fp16
__device__ __half g_XW2H[NN * DOUT];        // layer-2 transformed feats, fp16
__device__ float  g_S2S [NN];
__device__ float  g_S2D [NN];
__device__ float  g_X2E [(NN + BG) * DOUT]; // node rows + pooled rows
__device__ float  g_B1E [FIN * C1E];        // extended B for GEMM1
__device__ float  g_Q2S [C1];               // W2 @ a2_src
__device__ float  g_Q2D [C1];               // W2 @ a2_dst
__device__ __half g_W2H [DOUT * C1];        // W2 hi, transposed [n][k]
__device__ __half g_W2L [DOUT * C1];        // W2 lo, transposed [n][k]
__device__ __half g_FWH [DOUT * DOUT];      // fcw hi, transposed [n][k]
__device__ __half g_FWL [DOUT * DOUT];      // fcw lo, transposed [n][k]
__device__ int    g_DEG[NN];
__device__ int    g_ROWPTR[NN + 1];
__device__ int    g_ROWCUR[NN];
__device__ int    g_ESRT[ETOT];
__device__ int    g_BSUM[32];

__device__ __forceinline__ float leakyf(float x) { return x > 0.f ? x : NEG_SLOPE * x; }
__device__ __forceinline__ float eluf(float x)   { return x > 0.f ? x : __expf(x) - 1.f; }

// bf16 hi/lo split of two floats (GEMM1 only)
__device__ __forceinline__ void bfsplit2(float x0, float x1, unsigned& h, unsigned& l) {
    __nv_bfloat162 hv = __floats2bfloat162_rn(x0, x1);
    float r0 = x0 - __bfloat162float(hv.x);
    float r1 = x1 - __bfloat162float(hv.y);
    __nv_bfloat162 lv = __floats2bfloat162_rn(r0, r1);
    h = *reinterpret_cast<unsigned*>(&hv);
    l = *reinterpret_cast<unsigned*>(&lv);
}

__device__ __forceinline__ void mma16bf(float* d, const unsigned* a, const unsigned* b) {
    asm volatile(
        "mma.sync.aligned.m16n8k16.row.col.f32.bf16.bf16.f32 "
        "{%0,%1,%2,%3}, {%4,%5,%6,%7}, {%8,%9}, {%0,%1,%2,%3};\n"
        : "+f"(d[0]), "+f"(d[1]), "+f"(d[2]), "+f"(d[3])
        : "r"(a[0]), "r"(a[1]), "r"(a[2]), "r"(a[3]), "r"(b[0]), "r"(b[1]));
}

__device__ __forceinline__ void mma16f(float* d, const unsigned* a, const unsigned* b) {
    asm volatile(
        "mma.sync.aligned.m16n8k16.row.col.f32.f16.f16.f32 "
        "{%0,%1,%2,%3}, {%4,%5,%6,%7}, {%8,%9}, {%0,%1,%2,%3};\n"
        : "+f"(d[0]), "+f"(d[1]), "+f"(d[2]), "+f"(d[3])
        : "r"(a[0]), "r"(a[1]), "r"(a[2]), "r"(a[3]), "r"(b[0]), "r"(b[1]));
}

// GEMM1 epilogue store -> fp16 features + fp32 score cols
__device__ __forceinline__ void st_m2(int r, int c, float2 v) {
    if (c < C1) {
        *reinterpret_cast<__half2*>(g_XW1H + (size_t)r * C1 + c) =
            __floats2half2_rn(v.x, v.y);
    } else {
        int sc = c - C1;
        if (sc < NH) {
            g_S1S[r * NH + sc]     = v.x;
            g_S1S[r * NH + sc + 1] = v.y;
        } else if (sc < 20) {
            g_S1D[r * NH + sc - NH]     = v.x;
            g_S1D[r * NH + sc - NH + 1] = v.y;
        }
    }
}

// ---------------- GEMM1: bf16x3 (A fp32 feats, K=32) -------------------------
__global__ __launch_bounds__(256)
void k_tgemm1(const float* __restrict__ A, const float* __restrict__ B,
              int M, int N, int K) {
    __shared__ float As[16][136];
    __shared__ float Bs[16][136];
    const int tid  = threadIdx.x;
    const int lane = tid & 31;
    const int wid  = tid >> 5;
    const int qr   = lane >> 2;
    const int qc   = lane & 3;
    const int wm   = (wid & 3) * 32;
    const int wn   = (wid >> 2) * 64;
    const int row0 = blockIdx.x * 128;
    const int col0 = blockIdx.y * 128;

    float acc[2][8][4];
#pragma unroll
    for (int mf = 0; mf < 2; mf++)
#pragma unroll
        for (int nf = 0; nf < 8; nf++)
#pragma unroll
            for (int i = 0; i < 4; i++) acc[mf][nf][i] = 0.f;

    for (int k0 = 0; k0 < K; k0 += 16) {
#pragma unroll
        for (int i = 0; i < 2; i++) {
            int f = tid + i * 256;
            int r = f >> 2, c4 = (f & 3) * 4;
            float4 v = {0.f, 0.f, 0.f, 0.f};
            if (row0 + r < M)
                v = *reinterpret_cast<const float4*>(A + (size_t)(row0 + r) * K + k0 + c4);
            As[c4 + 0][r] = v.x; As[c4 + 1][r] = v.y;
            As[c4 + 2][r] = v.z; As[c4 + 3][r] = v.w;
        }
#pragma unroll
        for (int i = 0; i < 2; i++) {
            int f = tid + i * 256;
            int kk = f >> 5, c4 = (f & 31) * 4;
            float4 v = {0.f, 0.f, 0.f, 0.f};
            const float* src = B + (size_t)(k0 + kk) * N + col0 + c4;
            if (col0 + c4 + 3 < N) {
                v = *reinterpret_cast<const float4*>(src);
            } else {
                if (col0 + c4 + 0 < N) v.x = src[0];
                if (col0 + c4 + 1 < N) v.y = src[1];
                if (col0 + c4 + 2 < N) v.z = src[2];
                if (col0 + c4 + 3 < N) v.w = src[3];
            }
            *reinterpret_cast<float4*>(&Bs[kk][c4]) = v;
        }
        __syncthreads();

        unsigned ah[2][4], al[2][4], bh[8][2], bl[8][2];
#pragma unroll
        for (int mf = 0; mf < 2; mf++) {
            int mb = wm + mf * 16 + qr;
            bfsplit2(As[2*qc][mb],     As[2*qc+1][mb],     ah[mf][0], al[mf][0]);
            bfsplit2(As[2*qc][mb+8],   As[2*qc+1][mb+8],   ah[mf][1], al[mf][1]);
            bfsplit2(As[2*qc+8][mb],   As[2*qc+9][mb],     ah[mf][2], al[mf][2]);
            bfsplit2(As[2*qc+8][mb+8], As[2*qc+9][mb+8],   ah[mf][3], al[mf][3]);
        }
#pragma unroll
        for (int nf = 0; nf < 8; nf++) {
            int nb = wn + nf * 8 + qr;
            bfsplit2(Bs[2*qc][nb],   Bs[2*qc+1][nb], bh[nf][0], bl[nf][0]);
            bfsplit2(Bs[2*qc+8][nb], Bs[2*qc+9][nb], bh[nf][1], bl[nf][1]);
        }
#pragma unroll
        for (int mf = 0; mf < 2; mf++)
#pragma unroll
            for (int nf = 0; nf < 8; nf++) {
                mma16bf(acc[mf][nf], ah[mf], bh[nf]);
                mma16bf(acc[mf][nf], al[mf], bh[nf]);
                mma16bf(acc[mf][nf], ah[mf], bl[nf]);
            }
        __syncthreads();
    }

#pragma unroll
    for (int mf = 0; mf < 2; mf++) {
        int r0 = row0 + wm + mf * 16 + qr;
#pragma unroll
        for (int nf = 0; nf < 8; nf++) {
            int c = col0 + wn + nf * 8 + 2 * qc;
            if (r0 < M)     st_m2(r0, c, make_float2(acc[mf][nf][0], acc[mf][nf][1]));
            if (r0 + 8 < M) st_m2(r0 + 8, c, make_float2(acc[mf][nf][2], acc[mf][nf][3]));
        }
    }
}

// ---------------- fp16 2-term GEMM (A fp16-precision, B pre-split hi/lo) -----
// 128x128 tile, BK=16, 256 threads, N == 128 (col0 == 0).
// MODE 4: A = __half*, out fp16 -> g_XW2H.   MODE 1: A = float*, out = bias+relu fp32.
template <int MODE, typename AT>
__global__ __launch_bounds__(256)
void k_hgemm(const AT* __restrict__ A, const __half* __restrict__ BhT,
             const __half* __restrict__ BlT, const float* __restrict__ bias,
             float* __restrict__ C, int M, int K) {
    __shared__ __half As [128][24];
    __shared__ __half Bhs[128][24];
    __shared__ __half Bls[128][24];
    const int tid  = threadIdx.x;
    const int lane = tid & 31;
    const int wid  = tid >> 5;
    const int qr   = lane >> 2;
    const int qc   = lane & 3;
    const int wm   = (wid & 3) * 32;
    const int wn   = (wid >> 2) * 64;
    const int row0 = blockIdx.x * 128;

    float acc[2][8][4];
#pragma unroll
    for (int mf = 0; mf < 2; mf++)
#pragma unroll
        for (int nf = 0; nf < 8; nf++)
#pragma unroll
            for (int i = 0; i < 4; i++) acc[mf][nf][i] = 0.f;

    const int r  = tid >> 1;
    const int c8 = (tid & 1) * 8;

    for (int k0 = 0; k0 < K; k0 += 16) {
        // A tile 128x16 -> fp16 smem [m][k]
        if (sizeof(AT) == 2) {
            uint4 v = {0u, 0u, 0u, 0u};
            if (row0 + r < M)
                v = *reinterpret_cast<const uint4*>(
                        reinterpret_cast<const __half*>(A) + (size_t)(row0 + r) * K + k0 + c8);
            *reinterpret_cast<uint4*>(&As[r][c8]) = v;
        } else {
            float4 v0 = {0,0,0,0}, v1 = {0,0,0,0};
            if (row0 + r < M) {
                const float* src = reinterpret_cast<const float*>(A) + (size_t)(row0 + r) * K + k0 + c8;
                v0 = *reinterpret_cast<const float4*>(src);
                v1 = *reinterpret_cast<const float4*>(src + 4);
            }
            *reinterpret_cast<__half2*>(&As[r][c8 + 0]) = __floats2half2_rn(v0.x, v0.y);
            *reinterpret_cast<__half2*>(&As[r][c8 + 2]) = __floats2half2_rn(v0.z, v0.w);
            *reinterpret_cast<__half2*>(&As[r][c8 + 4]) = __floats2half2_rn(v1.x, v1.y);
            *reinterpret_cast<__half2*>(&As[r][c8 + 6]) = __floats2half2_rn(v1.z, v1.w);
        }
        // B tiles (pre-transposed [n][k]): rows are n, coalesced uint4 loads
        {
            uint4 vh = *reinterpret_cast<const uint4*>(BhT + (size_t)r * K + k0 + c8);
            uint4 vl = *reinterpret_cast<const uint4*>(BlT + (size_t)r * K + k0 + c8);
            *reinterpret_cast<uint4*>(&Bhs[r][c8]) = vh;
            *reinterpret_cast<uint4*>(&Bls[r][c8]) = vl;
        }
        __syncthreads();

        unsigned a[2][4], bh[8][2], bl[8][2];
#pragma unroll
        for (int mf = 0; mf < 2; mf++) {
            int mb = wm + mf * 16 + qr;
            a[mf][0] = *reinterpret_cast<const unsigned*>(&As[mb][2 * qc]);
            a[mf][1] = *reinterpret_cast<const unsigned*>(&As[mb + 8][2 * qc]);
            a[mf][2] = *reinterpret_cast<const unsigned*>(&As[mb][2 * qc + 8]);
            a[mf][3] = *reinterpret_cast<const unsigned*>(&As[mb + 8][2 * qc + 8]);
        }
#pragma unroll
        for (int nf = 0; nf < 8; nf++) {
            int nb = wn + nf * 8 + qr;
            bh[nf][0] = *reinterpret_cast<const unsigned*>(&Bhs[nb][2 * qc]);
            bh[nf][1] = *reinterpret_cast<const unsigned*>(&Bhs[nb][2 * qc + 8]);
            bl[nf][0] = *reinterpret_cast<const unsigned*>(&Bls[nb][2 * qc]);
            bl[nf][1] = *reinterpret_cast<const unsigned*>(&Bls[nb][2 * qc + 8]);
        }
#pragma unroll
        for (int mf = 0; mf < 2; mf++)
#pragma unroll
            for (int nf = 0; nf < 8; nf++) {
                mma16f(acc[mf][nf], a[mf], bh[nf]);
                mma16f(acc[mf][nf], a[mf], bl[nf]);
            }
        __syncthreads();
    }

#pragma unroll
    for (int mf = 0; mf < 2; mf++) {
        int r0 = row0 + wm + mf * 16 + qr;
#pragma unroll
        for (int nf = 0; nf < 8; nf++) {
            int c = wn + nf * 8 + 2 * qc;
            float2 v0 = {acc[mf][nf][0], acc[mf][nf][1]};
            float2 v1 = {acc[mf][nf][2], acc[mf][nf][3]};
            if (MODE == 1) {
                float bc0 = bias[c], bc1 = bias[c + 1];
                v0.x = fmaxf(v0.x + bc0, 0.f); v0.y = fmaxf(v0.y + bc1, 0.f);
                v1.x = fmaxf(v1.x + bc0, 0.f); v1.y = fmaxf(v1.y + bc1, 0.f);
                if (r0 < M)
                    *reinterpret_cast<float2*>(C + (size_t)r0 * DOUT + c) = v0;
                if (r0 + 8 < M)
                    *reinterpret_cast<float2*>(C + (size_t)(r0 + 8) * DOUT + c) = v1;
            } else {
                if (r0 < M)
                    *reinterpret_cast<__half2*>(g_XW2H + (size_t)r0 * DOUT + c) =
                        __floats2half2_rn(v0.x, v0.y);
                if (r0 + 8 < M)
                    *reinterpret_cast<__half2*>(g_XW2H + (size_t)(r0 + 8) * DOUT + c) =
                        __floats2half2_rn(v1.x, v1.y);
            }
        }
    }
}

// ---------------- build extended B1 [32 x 340] -------------------------------
__global__ void k_bext1(const float* __restrict__ W1, const float* __restrict__ a1s,
                        const float* __restrict__ a1d) {
    int k = blockIdx.x;
    int j = threadIdx.x;
    if (j >= C1E) return;
    float v;
    if (j < C1) {
        v = W1[k * C1 + j];
    } else if (j < C1 + NH) {
        int h = j - C1;
        float s = 0.f;
        for (int f = 0; f < FIN; f++)
            s += W1[k * C1 + h * FIN + f] * a1s[h * FIN + f];
        v = s;
    } else {
        int h = j - C1 - NH;
        float s = 0.f;
        for (int f = 0; f < FIN; f++)
            s += W1[k * C1 + h * FIN + f] * a1d[h * FIN + f];
        v = s;
    }
    g_B1E[k * C1E + j] = v;
}

// ---------------- weight prep: W2/fcw fp16 split+transpose, Q2 ---------------
#define PREP_W2  (C1 * DOUT)                 // 40960
#define PREP_FC  (PREP_W2 + DOUT * DOUT)     // 57344 (divisible by 256)
__global__ void k_prep2(const float* __restrict__ W2, const float* __restrict__ fcw,
                        const float* __restrict__ a2s, const float* __restrict__ a2d) {
    int gid = blockIdx.x * 256 + threadIdx.x;
    if (gid < PREP_W2) {
        int k = gid / DOUT, n = gid % DOUT;
        float w = W2[gid];
        __half h = __float2half_rn(w);
        g_W2H[n * C1 + k] = h;
        g_W2L[n * C1 + k] = __float2half_rn(w - __half2float(h));
    } else if (gid < PREP_FC) {
        int e = gid - PREP_W2;
        int k = e / DOUT, n = e % DOUT;
        float w = fcw[e];
        __half h = __float2half_rn(w);
        g_FWH[n * DOUT + k] = h;
        g_FWL[n * DOUT + k] = __float2half_rn(w - __half2float(h));
    } else {
        int t = gid - PREP_FC;
        int k = t >> 5, lane = t & 31;
        if (k >= C1) return;
        float s = 0.f, d = 0.f;
#pragma unroll
        for (int j = 0; j < 4; j++) {
            float w = W2[k * DOUT + j * 32 + lane];
            s += w * a2s[j * 32 + lane];
            d += w * a2d[j * 32 + lane];
        }
#pragma unroll
        for (int o = 16; o > 0; o >>= 1) {
            s += __shfl_down_sync(0xffffffffu, s, o);
            d += __shfl_down_sync(0xffffffffu, d, o);
        }
        if (lane == 0) { g_Q2S[k] = s; g_Q2D[k] = d; }
    }
}

// ---------------- CSR build ---------------------------------------------------
__global__ void k_count(const int* __restrict__ edst) {
    int e = blockIdx.x * blockDim.x + threadIdx.x;
    if (e < EE) atomicAdd(&g_DEG[edst[e]], 1);
}

__global__ void k_scanA() {                    // 20 blocks x 1024
    __shared__ int sh[1024];
    int b = blockIdx.x, t = threadIdx.x;
    int n = b * 1024 + t;
    int v = (n < NN) ? g_DEG[n] + 1 : 0;
    sh[t] = v;
    __syncthreads();
    for (int o = 1; o < 1024; o <<= 1) {
        int u = (t >= o) ? sh[t - o] : 0;
        __syncthreads();
        sh[t] += u;
        __syncthreads();
    }
    if (n < NN) g_ROWPTR[n] = sh[t] - v;
    if (t == 1023) g_BSUM[b] = sh[t];
}

__global__ void k_scanC() {                    // 20 blocks x 1024, inline top scan
    __shared__ int boff;
    int b = blockIdx.x, t = threadIdx.x;
    if (t < 32) {
        int v = (t < 20) ? g_BSUM[t] : 0;
        int orig = v;
#pragma unroll
        for (int o = 1; o < 32; o <<= 1) {
            int u = __shfl_up_sync(0xffffffffu, v, o);
            if (t >= o) v += u;
        }
        if (t == b) boff = v - orig;           // exclusive prefix for this block
    }
    __syncthreads();
    int n = b * 1024 + t;
    if (n < NN) {
        int rr = g_ROWPTR[n] + boff;
        g_ROWPTR[n] = rr;
        g_ROWCUR[n] = rr;
    }
    if (b == 0 && t == 0) g_ROWPTR[NN] = ETOT;
}

__global__ void k_scatter(const int* __restrict__ esrc, const int* __restrict__ edst) {
    int e = blockIdx.x * blockDim.x + threadIdx.x;
    if (e >= ETOT) return;
    int s, d;
    if (e < EE) { s = esrc[e]; d = edst[e]; } else { s = d = e - EE; }
    int pos = atomicAdd(&g_ROWCUR[d], 1);
    g_ESRT[pos] = s;
}

// ---------------- layer-1 aggregation over fp16 xw rows ----------------------
__global__ void k_agg1(const float* __restrict__ b1) {
    int lane = threadIdx.x & 31;
    int n = (blockIdx.x * blockDim.x + threadIdx.x) >> 5;
    if (n >= NN) return;
    int p0 = g_ROWPTR[n], p1 = g_ROWPTR[n + 1];
    float sd = (lane < NH) ? g_S1D[n * NH + lane] : 0.f;
    int hbase = lane >> 4;

    float2 acc[5];
#pragma unroll
    for (int j = 0; j < 5; j++) acc[j] = make_float2(0.f, 0.f);
    float denom = 0.f;

    int s_next = g_ESRT[p0];
    for (int k = p0; k < p1; k++) {
        int s = s_next;
        if (k + 1 < p1) s_next = g_ESRT[k + 1];
        float ex = (lane < NH) ? __expf(leakyf(g_S1S[s * NH + lane] + sd)) : 0.f;
        denom += ex;
        const __half2* row = reinterpret_cast<const __half2*>(g_XW1H + (size_t)s * C1);
#pragma unroll
        for (int j = 0; j < 5; j++) {
            float a = __shfl_sync(0xffffffffu, ex, hbase + 2 * j);
            float2 v = __half22float2(row[lane + 32 * j]);
            acc[j].x = fmaf(a, v.x, acc[j].x);
            acc[j].y = fmaf(a, v.y, acc[j].y);
        }
    }

    float vs = 0.f, vd = 0.f;
#pragma unroll
    for (int j = 0; j < 5; j++) {
        float d = fmaxf(__shfl_sync(0xffffffffu, denom, hbase + 2 * j), 1e-16f);
        int w = lane + 32 * j;
        float2 b = reinterpret_cast<const float2*>(b1)[w];
        float ox = eluf(acc[j].x / d + b.x);
        float oy = eluf(acc[j].y / d + b.y);
        *reinterpret_cast<__half2*>(g_X1H + (size_t)n * C1 + 2 * w) =
            __floats2half2_rn(ox, oy);
        vs += ox * g_Q2S[2 * w] + oy * g_Q2S[2 * w + 1];
        vd += ox * g_Q2D[2 * w] + oy * g_Q2D[2 * w + 1];
    }
#pragma unroll
    for (int o = 16; o > 0; o >>= 1) {
        vs += __shfl_down_sync(0xffffffffu, vs, o);
        vd += __shfl_down_sync(0xffffffffu, vd, o);
    }
    if (lane == 0) { g_S2S[n] = vs; g_S2D[n] = vd; }
}

// ---------------- layer-2 aggregation (fp16 gather) + fused max-pool ---------
__global__ void k_agg2(const float* __restrict__ b2) {
    int lane = threadIdx.x & 31;
    int n = (blockIdx.x * blockDim.x + threadIdx.x) >> 5;
    if (n >= NN) return;
    int p0 = g_ROWPTR[n], p1 = g_ROWPTR[n + 1];
    float sd = g_S2D[n];

    float2 acc0 = {0.f, 0.f}, acc1 = {0.f, 0.f};
    float denom = 0.f;
    int s_next = g_ESRT[p0];
    for (int k = p0; k < p1; k++) {
        int s = s_next;
        if (k + 1 < p1) s_next = g_ESRT[k + 1];
        float ex = __expf(leakyf(g_S2S[s] + sd));
        denom += ex;
        const __half2* row = reinterpret_cast<const __half2*>(g_XW2H + (size_t)s * DOUT);
        float2 v0 = __half22float2(row[lane]);
        float2 v1 = __half22float2(row[lane + 32]);
        acc0.x = fmaf(ex, v0.x, acc0.x); acc0.y = fmaf(ex, v0.y, acc0.y);
        acc1.x = fmaf(ex, v1.x, acc1.x); acc1.y = fmaf(ex, v1.y, acc1.y);
    }
    float dn = fmaxf(denom, 1e-16f);
    float2 b0 = reinterpret_cast<const float2*>(b2)[lane];
    float2 b1v = reinterpret_cast<const float2*>(b2)[lane + 32];
    float2 o0, o1;
    o0.x = fmaxf(acc0.x / dn + b0.x, 0.f);
    o0.y = fmaxf(acc0.y / dn + b0.y, 0.f);
    o1.x = fmaxf(acc1.x / dn + b1v.x, 0.f);
    o1.y = fmaxf(acc1.y / dn + b1v.y, 0.f);
    *reinterpret_cast<float2*>(g_X2E + (size_t)n * DOUT + 2 * lane) = o0;
    *reinterpret_cast<float2*>(g_X2E + (size_t)n * DOUT + 64 + 2 * lane) = o1;

    int grow = NN + n / PERN;
    int* pm0 = reinterpret_cast<int*>(g_X2E + (size_t)grow * DOUT + 2 * lane);
    int* pm1 = reinterpret_cast<int*>(g_X2E + (size_t)grow * DOUT + 64 + 2 * lane);
    atomicMax(pm0 + 0, __float_as_int(o0.x));
    atomicMax(pm0 + 1, __float_as_int(o0.y));
    atomicMax(pm1 + 0, __float_as_int(o1.x));
    atomicMax(pm1 + 1, __float_as_int(o1.y));
}

// ============================================================================
extern "C" void kernel_launch(void* const* d_in, const int* in_sizes, int n_in,
                              void* d_out, int out_size) {
    const float* feats = (const float*)d_in[0];
    const int*   ei    = (const int*)d_in[1];
    const int*   esrc  = ei;
    const int*   edst  = ei + EE;
    const float* W1  = (const float*)d_in[4];
    const float* a1s = (const float*)d_in[5];
    const float* a1d = (const float*)d_in[6];
    const float* b1  = (const float*)d_in[7];
    const float* W2  = (const float*)d_in[8];
    const float* a2s = (const float*)d_in[9];
    const float* a2d = (const float*)d_in[10];
    const float* b2  = (const float*)d_in[11];
    const float* fcw = (const float*)d_in[12];
    const float* fcb = (const float*)d_in[13];
    float* out = (float*)d_out;

    void *pX1H, *pX2E, *pB1E, *pDEG, *pW2H, *pW2L, *pFWH, *pFWL;
    cudaGetSymbolAddress(&pX1H, g_X1H);
    cudaGetSymbolAddress(&pX2E, g_X2E);
    cudaGetSymbolAddress(&pB1E, g_B1E);
    cudaGetSymbolAddress(&pDEG, g_DEG);
    cudaGetSymbolAddress(&pW2H, g_W2H);
    cudaGetSymbolAddress(&pW2L, g_W2L);
    cudaGetSymbolAddress(&pFWH, g_FWH);
    cudaGetSymbolAddress(&pFWL, g_FWL);

    const int WB = 256;
    int warpBlocks = (NN * 32 + WB - 1) / WB;

    cudaMemsetAsync(pDEG, 0, NN * sizeof(int));
    cudaMemsetAsync((float*)pX2E + (size_t)NN * DOUT, 0, BG * DOUT * sizeof(float));

    // CSR build + weight preprocessing
    k_count<<<(EE + 255) / 256, 256>>>(edst);
    k_bext1<<<FIN, 352>>>(W1, a1s, a1d);
    k_prep2<<<(PREP_FC + C1 * 32) / 256, 256>>>(W2, fcw, a2s, a2d);
    k_scanA<<<20, 1024>>>();
    k_scanC<<<20, 1024>>>();
    k_scatter<<<(ETOT + 255) / 256, 256>>>(esrc, edst);

    // GEMM1: [20000,32] @ [32,340] -> fp16 feats + fp32 scores
    dim3 g1((NN + 127) / 128, (C1E + 127) / 128);
    k_tgemm1<<<g1, 256>>>(feats, (const float*)pB1E, NN, C1E, FIN);

    // layer-1 aggregation (+ bias + elu + X1H store + layer-2 scores)
    k_agg1<<<warpBlocks, WB>>>(b1);

    // GEMM2: X1H[20000,320] @ W2 -> fp16 XW2H  (fp16 2-term)
    k_hgemm<4, __half><<<(NN + 127) / 128, 256>>>(
        (const __half*)pX1H, (const __half*)pW2H, (const __half*)pW2L,
        nullptr, nullptr, NN, C1);

    // layer-2 aggregation + pool
    k_agg2<<<warpBlocks, WB>>>(b2);

    // FC over node rows + pooled rows -> entire output (fp16 2-term)
    k_hgemm<1, float><<<(NN + BG + 127) / 128, 256>>>(
        (const float*)pX2E, (const __half*)pFWH, (const __half*)pFWL,
        fcb, out, NN + BG, DOUT);
}

// round 10
// speedup vs baseline: 1.9983x; 1.0243x over previous
#include <cuda_runtime.h>
#include <cuda_fp16.h>
#include <cuda_bf16.h>

#define NN    20000
#define BG    100
#define PERN  200
#define EE    320000
#define ETOT  340000
#define FIN   32
#define NH    10
#define C1    320
#define C1E   340
#define DOUT  128
#define NEG_SLOPE 0.2f

// ---------------- scratch ----------------------------------------------------
__device__ __half g_XW1H[NN * C1];
__device__ float  g_S1S [NN * NH];
__device__ float  g_S1D [NN * NH];
__device__ __half g_X1H [NN * C1];
__device__ __half g_XW2H[NN * DOUT];
__device__ float  g_S2S [NN];
__device__ float  g_S2D [NN];
__device__ float  g_X2E [(NN + BG) * DOUT];
__device__ float  g_B1E [FIN * C1E];
__device__ float  g_Q2S [C1];
__device__ float  g_Q2D [C1];
__device__ __half g_W2H [DOUT * C1];
__device__ __half g_W2L [DOUT * C1];
__device__ __half g_FWH [DOUT * DOUT];
__device__ __half g_FWL [DOUT * DOUT];
__device__ int    g_DEG[NN + 32];           // [NN..NN+20) = lookback flags
__device__ int    g_ROWPTR[NN + 1];
__device__ int    g_ROWCUR[NN];
__device__ int    g_ESRT[ETOT];
__device__ int    g_BSUM[32];

__device__ __forceinline__ float leakyf(float x) { return x > 0.f ? x : NEG_SLOPE * x; }
__device__ __forceinline__ float eluf(float x)   { return x > 0.f ? x : __expf(x) - 1.f; }

__device__ __forceinline__ void bfsplit2(float x0, float x1, unsigned& h, unsigned& l) {
    __nv_bfloat162 hv = __floats2bfloat162_rn(x0, x1);
    float r0 = x0 - __bfloat162float(hv.x);
    float r1 = x1 - __bfloat162float(hv.y);
    __nv_bfloat162 lv = __floats2bfloat162_rn(r0, r1);
    h = *reinterpret_cast<unsigned*>(&hv);
    l = *reinterpret_cast<unsigned*>(&lv);
}

__device__ __forceinline__ void mma16bf(float* d, const unsigned* a, const unsigned* b) {
    asm volatile(
        "mma.sync.aligned.m16n8k16.row.col.f32.bf16.bf16.f32 "
        "{%0,%1,%2,%3}, {%4,%5,%6,%7}, {%8,%9}, {%0,%1,%2,%3};\n"
        : "+f"(d[0]), "+f"(d[1]), "+f"(d[2]), "+f"(d[3])
        : "r"(a[0]), "r"(a[1]), "r"(a[2]), "r"(a[3]), "r"(b[0]), "r"(b[1]));
}

__device__ __forceinline__ void mma16f(float* d, const unsigned* a, const unsigned* b) {
    asm volatile(
        "mma.sync.aligned.m16n8k16.row.col.f32.f16.f16.f32 "
        "{%0,%1,%2,%3}, {%4,%5,%6,%7}, {%8,%9}, {%0,%1,%2,%3};\n"
        : "+f"(d[0]), "+f"(d[1]), "+f"(d[2]), "+f"(d[3])
        : "r"(a[0]), "r"(a[1]), "r"(a[2]), "r"(a[3]), "r"(b[0]), "r"(b[1]));
}

__device__ __forceinline__ void st_m2(int r, int c, float2 v) {
    if (c < C1) {
        *reinterpret_cast<__half2*>(g_XW1H + (size_t)r * C1 + c) =
            __floats2half2_rn(v.x, v.y);
    } else {
        int sc = c - C1;
        if (sc < NH) {
            g_S1S[r * NH + sc]     = v.x;
            g_S1S[r * NH + sc + 1] = v.y;
        } else if (sc < 20) {
            g_S1D[r * NH + sc - NH]     = v.x;
            g_S1D[r * NH + sc - NH + 1] = v.y;
        }
    }
}

// ---------------- GEMM1: bf16x3 (A fp32 feats, K=32) -------------------------
__global__ __launch_bounds__(256)
void k_tgemm1(const float* __restrict__ A, const float* __restrict__ B,
              int M, int N, int K) {
    __shared__ float As[16][136];
    __shared__ float Bs[16][136];
    const int tid  = threadIdx.x;
    const int lane = tid & 31;
    const int wid  = tid >> 5;
    const int qr   = lane >> 2;
    const int qc   = lane & 3;
    const int wm   = (wid & 3) * 32;
    const int wn   = (wid >> 2) * 64;
    const int row0 = blockIdx.x * 128;
    const int col0 = blockIdx.y * 128;

    float acc[2][8][4];
#pragma unroll
    for (int mf = 0; mf < 2; mf++)
#pragma unroll
        for (int nf = 0; nf < 8; nf++)
#pragma unroll
            for (int i = 0; i < 4; i++) acc[mf][nf][i] = 0.f;

    for (int k0 = 0; k0 < K; k0 += 16) {
#pragma unroll
        for (int i = 0; i < 2; i++) {
            int f = tid + i * 256;
            int r = f >> 2, c4 = (f & 3) * 4;
            float4 v = {0.f, 0.f, 0.f, 0.f};
            if (row0 + r < M)
                v = *reinterpret_cast<const float4*>(A + (size_t)(row0 + r) * K + k0 + c4);
            As[c4 + 0][r] = v.x; As[c4 + 1][r] = v.y;
            As[c4 + 2][r] = v.z; As[c4 + 3][r] = v.w;
        }
#pragma unroll
        for (int i = 0; i < 2; i++) {
            int f = tid + i * 256;
            int kk = f >> 5, c4 = (f & 31) * 4;
            float4 v = {0.f, 0.f, 0.f, 0.f};
            const float* src = B + (size_t)(k0 + kk) * N + col0 + c4;
            if (col0 + c4 + 3 < N) {
                v = *reinterpret_cast<const float4*>(src);
            } else {
                if (col0 + c4 + 0 < N) v.x = src[0];
                if (col0 + c4 + 1 < N) v.y = src[1];
                if (col0 + c4 + 2 < N) v.z = src[2];
                if (col0 + c4 + 3 < N) v.w = src[3];
            }
            *reinterpret_cast<float4*>(&Bs[kk][c4]) = v;
        }
        __syncthreads();

        unsigned ah[2][4], al[2][4], bh[8][2], bl[8][2];
#pragma unroll
        for (int mf = 0; mf < 2; mf++) {
            int mb = wm + mf * 16 + qr;
            bfsplit2(As[2*qc][mb],     As[2*qc+1][mb],     ah[mf][0], al[mf][0]);
            bfsplit2(As[2*qc][mb+8],   As[2*qc+1][mb+8],   ah[mf][1], al[mf][1]);
            bfsplit2(As[2*qc+8][mb],   As[2*qc+9][mb],     ah[mf][2], al[mf][2]);
            bfsplit2(As[2*qc+8][mb+8], As[2*qc+9][mb+8],   ah[mf][3], al[mf][3]);
        }
#pragma unroll
        for (int nf = 0; nf < 8; nf++) {
            int nb = wn + nf * 8 + qr;
            bfsplit2(Bs[2*qc][nb],   Bs[2*qc+1][nb], bh[nf][0], bl[nf][0]);
            bfsplit2(Bs[2*qc+8][nb], Bs[2*qc+9][nb], bh[nf][1], bl[nf][1]);
        }
#pragma unroll
        for (int mf = 0; mf < 2; mf++)
#pragma unroll
            for (int nf = 0; nf < 8; nf++) {
                mma16bf(acc[mf][nf], ah[mf], bh[nf]);
                mma16bf(acc[mf][nf], al[mf], bh[nf]);
                mma16bf(acc[mf][nf], ah[mf], bl[nf]);
            }
        __syncthreads();
    }

#pragma unroll
    for (int mf = 0; mf < 2; mf++) {
        int r0 = row0 + wm + mf * 16 + qr;
#pragma unroll
        for (int nf = 0; nf < 8; nf++) {
            int c = col0 + wn + nf * 8 + 2 * qc;
            if (r0 < M)     st_m2(r0, c, make_float2(acc[mf][nf][0], acc[mf][nf][1]));
            if (r0 + 8 < M) st_m2(r0 + 8, c, make_float2(acc[mf][nf][2], acc[mf][nf][3]));
        }
    }
}

// ---------------- fp16 2-term GEMM ------------------------------------------
template <int MODE, typename AT>
__global__ __launch_bounds__(256)
void k_hgemm(const AT* __restrict__ A, const __half* __restrict__ BhT,
             const __half* __restrict__ BlT, const float* __restrict__ bias,
             float* __restrict__ C, int M, int K) {
    __shared__ __half As [128][24];
    __shared__ __half Bhs[128][24];
    __shared__ __half Bls[128][24];
    const int tid  = threadIdx.x;
    const int lane = tid & 31;
    const int wid  = tid >> 5;
    const int qr   = lane >> 2;
    const int qc   = lane & 3;
    const int wm   = (wid & 3) * 32;
    const int wn   = (wid >> 2) * 64;
    const int row0 = blockIdx.x * 128;

    float acc[2][8][4];
#pragma unroll
    for (int mf = 0; mf < 2; mf++)
#pragma unroll
        for (int nf = 0; nf < 8; nf++)
#pragma unroll
            for (int i = 0; i < 4; i++) acc[mf][nf][i] = 0.f;

    const int r  = tid >> 1;
    const int c8 = (tid & 1) * 8;

    for (int k0 = 0; k0 < K; k0 += 16) {
        if (sizeof(AT) == 2) {
            uint4 v = {0u, 0u, 0u, 0u};
            if (row0 + r < M)
                v = *reinterpret_cast<const uint4*>(
                        reinterpret_cast<const __half*>(A) + (size_t)(row0 + r) * K + k0 + c8);
            *reinterpret_cast<uint4*>(&As[r][c8]) = v;
        } else {
            float4 v0 = {0,0,0,0}, v1 = {0,0,0,0};
            if (row0 + r < M) {
                const float* src = reinterpret_cast<const float*>(A) + (size_t)(row0 + r) * K + k0 + c8;
                v0 = *reinterpret_cast<const float4*>(src);
                v1 = *reinterpret_cast<const float4*>(src + 4);
            }
            *reinterpret_cast<__half2*>(&As[r][c8 + 0]) = __floats2half2_rn(v0.x, v0.y);
            *reinterpret_cast<__half2*>(&As[r][c8 + 2]) = __floats2half2_rn(v0.z, v0.w);
            *reinterpret_cast<__half2*>(&As[r][c8 + 4]) = __floats2half2_rn(v1.x, v1.y);
            *reinterpret_cast<__half2*>(&As[r][c8 + 6]) = __floats2half2_rn(v1.z, v1.w);
        }
        {
            uint4 vh = *reinterpret_cast<const uint4*>(BhT + (size_t)r * K + k0 + c8);
            uint4 vl = *reinterpret_cast<const uint4*>(BlT + (size_t)r * K + k0 + c8);
            *reinterpret_cast<uint4*>(&Bhs[r][c8]) = vh;
            *reinterpret_cast<uint4*>(&Bls[r][c8]) = vl;
        }
        __syncthreads();

        unsigned a[2][4], bh[8][2], bl[8][2];
#pragma unroll
        for (int mf = 0; mf < 2; mf++) {
            int mb = wm + mf * 16 + qr;
            a[mf][0] = *reinterpret_cast<const unsigned*>(&As[mb][2 * qc]);
            a[mf][1] = *reinterpret_cast<const unsigned*>(&As[mb + 8][2 * qc]);
            a[mf][2] = *reinterpret_cast<const unsigned*>(&As[mb][2 * qc + 8]);
            a[mf][3] = *reinterpret_cast<const unsigned*>(&As[mb + 8][2 * qc + 8]);
        }
#pragma unroll
        for (int nf = 0; nf < 8; nf++) {
            int nb = wn + nf * 8 + qr;
            bh[nf][0] = *reinterpret_cast<const unsigned*>(&Bhs[nb][2 * qc]);
            bh[nf][1] = *reinterpret_cast<const unsigned*>(&Bhs[nb][2 * qc + 8]);
            bl[nf][0] = *reinterpret_cast<const unsigned*>(&Bls[nb][2 * qc]);
            bl[nf][1] = *reinterpret_cast<const unsigned*>(&Bls[nb][2 * qc + 8]);
        }
#pragma unroll
        for (int mf = 0; mf < 2; mf++)
#pragma unroll
            for (int nf = 0; nf < 8; nf++) {
                mma16f(acc[mf][nf], a[mf], bh[nf]);
                mma16f(acc[mf][nf], a[mf], bl[nf]);
            }
        __syncthreads();
    }

#pragma unroll
    for (int mf = 0; mf < 2; mf++) {
        int r0 = row0 + wm + mf * 16 + qr;
#pragma unroll
        for (int nf = 0; nf < 8; nf++) {
            int c = wn + nf * 8 + 2 * qc;
            float2 v0 = {acc[mf][nf][0], acc[mf][nf][1]};
            float2 v1 = {acc[mf][nf][2], acc[mf][nf][3]};
            if (MODE == 1) {
                float bc0 = bias[c], bc1 = bias[c + 1];
                v0.x = fmaxf(v0.x + bc0, 0.f); v0.y = fmaxf(v0.y + bc1, 0.f);
                v1.x = fmaxf(v1.x + bc0, 0.f); v1.y = fmaxf(v1.y + bc1, 0.f);
                if (r0 < M)
                    *reinterpret_cast<float2*>(C + (size_t)r0 * DOUT + c) = v0;
                if (r0 + 8 < M)
                    *reinterpret_cast<float2*>(C + (size_t)(r0 + 8) * DOUT + c) = v1;
            } else {
                if (r0 < M)
                    *reinterpret_cast<__half2*>(g_XW2H + (size_t)r0 * DOUT + c) =
                        __floats2half2_rn(v0.x, v0.y);
                if (r0 + 8 < M)
                    *reinterpret_cast<__half2*>(g_XW2H + (size_t)(r0 + 8) * DOUT + c) =
                        __floats2half2_rn(v1.x, v1.y);
            }
        }
    }
}

// ---------------- merged prep: edge count + B1E + W2/fcw split + Q2 ----------
#define CNT_BLKS  910                              // ceil(EE/352)
#define BEXT_BLKS 32
#define PREP_W2   (C1 * DOUT)                      // 40960
#define PREP_FC   (PREP_W2 + DOUT * DOUT)          // 57344
#define PREP_TOT  (PREP_FC + C1 * 32)              // 67584
#define PREP_BLKS (PREP_TOT / 352)                 // 192
#define PRE_BLKS  (CNT_BLKS + BEXT_BLKS + PREP_BLKS)

__global__ __launch_bounds__(352)
void k_pre(const int* __restrict__ edst, const float* __restrict__ W1,
           const float* __restrict__ a1s, const float* __restrict__ a1d,
           const float* __restrict__ W2, const float* __restrict__ fcw,
           const float* __restrict__ a2s, const float* __restrict__ a2d) {
    int b = blockIdx.x, t = threadIdx.x;
    if (b < CNT_BLKS) {
        int e = b * 352 + t;
        if (e < EE) atomicAdd(&g_DEG[edst[e]], 1);
    } else if (b < CNT_BLKS + BEXT_BLKS) {
        int k = b - CNT_BLKS;
        int j = t;
        if (j >= C1E) return;
        float v;
        if (j < C1) {
            v = W1[k * C1 + j];
        } else if (j < C1 + NH) {
            int h = j - C1;
            float s = 0.f;
            for (int f = 0; f < FIN; f++)
                s += W1[k * C1 + h * FIN + f] * a1s[h * FIN + f];
            v = s;
        } else {
            int h = j - C1 - NH;
            float s = 0.f;
            for (int f = 0; f < FIN; f++)
                s += W1[k * C1 + h * FIN + f] * a1d[h * FIN + f];
            v = s;
        }
        g_B1E[k * C1E + j] = v;
    } else {
        int gid = (b - CNT_BLKS - BEXT_BLKS) * 352 + t;
        if (gid < PREP_W2) {
            int k = gid / DOUT, n = gid % DOUT;
            float w = W2[gid];
            __half h = __float2half_rn(w);
            g_W2H[n * C1 + k] = h;
            g_W2L[n * C1 + k] = __float2half_rn(w - __half2float(h));
        } else if (gid < PREP_FC) {
            int e = gid - PREP_W2;
            int k = e / DOUT, n = e % DOUT;
            float w = fcw[e];
            __half h = __float2half_rn(w);
            g_FWH[n * DOUT + k] = h;
            g_FWL[n * DOUT + k] = __float2half_rn(w - __half2float(h));
        } else {
            int t2 = gid - PREP_FC;
            int k = t2 >> 5, lane = t2 & 31;
            if (k >= C1) return;
            float s = 0.f, d = 0.f;
#pragma unroll
            for (int j = 0; j < 4; j++) {
                float w = W2[k * DOUT + j * 32 + lane];
                s += w * a2s[j * 32 + lane];
                d += w * a2d[j * 32 + lane];
            }
#pragma unroll
            for (int o = 16; o > 0; o >>= 1) {
                s += __shfl_down_sync(0xffffffffu, s, o);
                d += __shfl_down_sync(0xffffffffu, d, o);
            }
            if (lane == 0) { g_Q2S[k] = s; g_Q2D[k] = d; }
        }
    }
}

// ---------------- single-kernel scan with decoupled lookback ------------------
// 20 blocks x 1024. Also zeroes the pooled rows of X2E.
__global__ void k_scan() {
    __shared__ int sh[1024];
    __shared__ int s_boff;
    int* flags = g_DEG + NN;       // zeroed by the memset each call
    int b = blockIdx.x, t = threadIdx.x;
    int n = b * 1024 + t;
    int v = (n < NN) ? g_DEG[n] + 1 : 0;
    sh[t] = v;
    __syncthreads();
    for (int o = 1; o < 1024; o <<= 1) {
        int u = (t >= o) ? sh[t - o] : 0;
        __syncthreads();
        sh[t] += u;
        __syncthreads();
    }
    if (t == 1023) {
        g_BSUM[b] = sh[1023];
        __threadfence();
        atomicExch(&flags[b], 1);
    }
    if (t < 32) {
        int p = 0;
        if (t < b) {
            while (atomicAdd(&flags[t], 0) == 0) {}
            p = g_BSUM[t];
        }
#pragma unroll
        for (int o = 16; o > 0; o >>= 1)
            p += __shfl_down_sync(0xffffffffu, p, o);
        if (t == 0) s_boff = p;
    }
    __syncthreads();
    if (n < NN) {
        int r = sh[t] - v + s_boff;
        g_ROWPTR[n] = r;
        g_ROWCUR[n] = r;
    }
    if (b == 19 && t == 1023) g_ROWPTR[NN] = ETOT;
    if (n < BG * DOUT) g_X2E[(size_t)NN * DOUT + n] = 0.f;
}

__global__ void k_scatter(const int* __restrict__ esrc, const int* __restrict__ edst) {
    int e = blockIdx.x * blockDim.x + threadIdx.x;
    if (e >= ETOT) return;
    int s, d;
    if (e < EE) { s = esrc[e]; d = edst[e]; } else { s = d = e - EE; }
    int pos = atomicAdd(&g_ROWCUR[d], 1);
    g_ESRT[pos] = s;
}

// ---------------- layer-1 aggregation (fp16 gather, pipelined scores) --------
__global__ void k_agg1(const float* __restrict__ b1) {
    int lane = threadIdx.x & 31;
    int n = (blockIdx.x * blockDim.x + threadIdx.x) >> 5;
    if (n >= NN) return;
    int p0 = g_ROWPTR[n], p1 = g_ROWPTR[n + 1];
    float sd = (lane < NH) ? g_S1D[n * NH + lane] : 0.f;
    int hbase = lane >> 4;

    float2 acc[5];
#pragma unroll
    for (int j = 0; j < 5; j++) acc[j] = make_float2(0.f, 0.f);
    float denom = 0.f;

    int s = g_ESRT[p0];
    float sc = (lane < NH) ? g_S1S[s * NH + lane] : 0.f;
    for (int k = p0; k < p1; k++) {
        int s_cur = s;
        float sc_cur = sc;
        if (k + 1 < p1) {
            s = g_ESRT[k + 1];
            sc = (lane < NH) ? g_S1S[s * NH + lane] : 0.f;
        }
        float ex = (lane < NH) ? __expf(leakyf(sc_cur + sd)) : 0.f;
        denom += ex;
        const __half2* row = reinterpret_cast<const __half2*>(g_XW1H + (size_t)s_cur * C1);
#pragma unroll
        for (int j = 0; j < 5; j++) {
            float a = __shfl_sync(0xffffffffu, ex, hbase + 2 * j);
            float2 v = __half22float2(row[lane + 32 * j]);
            acc[j].x = fmaf(a, v.x, acc[j].x);
            acc[j].y = fmaf(a, v.y, acc[j].y);
        }
    }

    float vs = 0.f, vd = 0.f;
#pragma unroll
    for (int j = 0; j < 5; j++) {
        float d = fmaxf(__shfl_sync(0xffffffffu, denom, hbase + 2 * j), 1e-16f);
        int w = lane + 32 * j;
        float2 b = reinterpret_cast<const float2*>(b1)[w];
        float ox = eluf(acc[j].x / d + b.x);
        float oy = eluf(acc[j].y / d + b.y);
        *reinterpret_cast<__half2*>(g_X1H + (size_t)n * C1 + 2 * w) =
            __floats2half2_rn(ox, oy);
        vs += ox * g_Q2S[2 * w] + oy * g_Q2S[2 * w + 1];
        vd += ox * g_Q2D[2 * w] + oy * g_Q2D[2 * w + 1];
    }
#pragma unroll
    for (int o = 16; o > 0; o >>= 1) {
        vs += __shfl_down_sync(0xffffffffu, vs, o);
        vd += __shfl_down_sync(0xffffffffu, vd, o);
    }
    if (lane == 0) { g_S2S[n] = vs; g_S2D[n] = vd; }
}

// ---------------- layer-2 aggregation + fused max-pool ------------------------
__global__ void k_agg2(const float* __restrict__ b2) {
    int lane = threadIdx.x & 31;
    int n = (blockIdx.x * blockDim.x + threadIdx.x) >> 5;
    if (n >= NN) return;
    int p0 = g_ROWPTR[n], p1 = g_ROWPTR[n + 1];
    float sd = g_S2D[n];

    float2 acc0 = {0.f, 0.f}, acc1 = {0.f, 0.f};
    float denom = 0.f;
    int s = g_ESRT[p0];
    float sc = g_S2S[s];
    for (int k = p0; k < p1; k++) {
        int s_cur = s;
        float sc_cur = sc;
        if (k + 1 < p1) {
            s = g_ESRT[k + 1];
            sc = g_S2S[s];
        }
        float ex = __expf(leakyf(sc_cur + sd));
        denom += ex;
        const __half2* row = reinterpret_cast<const __half2*>(g_XW2H + (size_t)s_cur * DOUT);
        float2 v0 = __half22float2(row[lane]);
        float2 v1 = __half22float2(row[lane + 32]);
        acc0.x = fmaf(ex, v0.x, acc0.x); acc0.y = fmaf(ex, v0.y, acc0.y);
        acc1.x = fmaf(ex, v1.x, acc1.x); acc1.y = fmaf(ex, v1.y, acc1.y);
    }
    float dn = fmaxf(denom, 1e-16f);
    float2 b0 = reinterpret_cast<const float2*>(b2)[lane];
    float2 b1v = reinterpret_cast<const float2*>(b2)[lane + 32];
    float2 o0, o1;
    o0.x = fmaxf(acc0.x / dn + b0.x, 0.f);
    o0.y = fmaxf(acc0.y / dn + b0.y, 0.f);
    o1.x = fmaxf(acc1.x / dn + b1v.x, 0.f);
    o1.y = fmaxf(acc1.y / dn + b1v.y, 0.f);
    *reinterpret_cast<float2*>(g_X2E + (size_t)n * DOUT + 2 * lane) = o0;
    *reinterpret_cast<float2*>(g_X2E + (size_t)n * DOUT + 64 + 2 * lane) = o1;

    int grow = NN + n / PERN;
    int* pm0 = reinterpret_cast<int*>(g_X2E + (size_t)grow * DOUT + 2 * lane);
    int* pm1 = reinterpret_cast<int*>(g_X2E + (size_t)grow * DOUT + 64 + 2 * lane);
    atomicMax(pm0 + 0, __float_as_int(o0.x));
    atomicMax(pm0 + 1, __float_as_int(o0.y));
    atomicMax(pm1 + 0, __float_as_int(o1.x));
    atomicMax(pm1 + 1, __float_as_int(o1.y));
}

// ============================================================================
extern "C" void kernel_launch(void* const* d_in, const int* in_sizes, int n_in,
                              void* d_out, int out_size) {
    const float* feats = (const float*)d_in[0];
    const int*   ei    = (const int*)d_in[1];
    const int*   esrc  = ei;
    const int*   edst  = ei + EE;
    const float* W1  = (const float*)d_in[4];
    const float* a1s = (const float*)d_in[5];
    const float* a1d = (const float*)d_in[6];
    const float* b1  = (const float*)d_in[7];
    const float* W2  = (const float*)d_in[8];
    const float* a2s = (const float*)d_in[9];
    const float* a2d = (const float*)d_in[10];
    const float* b2  = (const float*)d_in[11];
    const float* fcw = (const float*)d_in[12];
    const float* fcb = (const float*)d_in[13];
    float* out = (float*)d_out;

    void *pX1H, *pX2E, *pB1E, *pDEG, *pW2H, *pW2L, *pFWH, *pFWL;
    cudaGetSymbolAddress(&pX1H, g_X1H);
    cudaGetSymbolAddress(&pX2E, g_X2E);
    cudaGetSymbolAddress(&pB1E, g_B1E);
    cudaGetSymbolAddress(&pDEG, g_DEG);
    cudaGetSymbolAddress(&pW2H, g_W2H);
    cudaGetSymbolAddress(&pW2L, g_W2L);
    cudaGetSymbolAddress(&pFWH, g_FWH);
    cudaGetSymbolAddress(&pFWL, g_FWL);

    // one-time side stream + fork/join events (host objects only; the enqueued
    // work is identical on every call)
    static cudaStream_t s2 = nullptr;
    static cudaEvent_t evF = nullptr, evJ = nullptr;
    if (!s2) {
        cudaStreamCreateWithFlags(&s2, cudaStreamNonBlocking);
        cudaEventCreateWithFlags(&evF, cudaEventDisableTiming);
        cudaEventCreateWithFlags(&evJ, cudaEventDisableTiming);
    }

    const int WB = 256;
    int warpBlocks = (NN * 32 + WB - 1) / WB;

    // zero degree counters + lookback flags (one memset)
    cudaMemsetAsync(pDEG, 0, (NN + 32) * sizeof(int));

    // merged prep: edge degree count + B1E + W2/fcw splits + Q2
    k_pre<<<PRE_BLKS, 352>>>(edst, W1, a1s, a1d, W2, fcw, a2s, a2d);

    // fork: GEMM1 on side stream, CSR scan+scatter on main stream
    cudaEventRecord(evF, 0);
    cudaStreamWaitEvent(s2, evF, 0);

    dim3 g1((NN + 127) / 128, (C1E + 127) / 128);
    k_tgemm1<<<g1, 256, 0, s2>>>(feats, (const float*)pB1E, NN, C1E, FIN);

    k_scan<<<20, 1024>>>();
    k_scatter<<<(ETOT + 255) / 256, 256>>>(esrc, edst);

    cudaEventRecord(evJ, s2);
    cudaStreamWaitEvent(0, evJ, 0);

    // layer-1 aggregation (+ bias + elu + X1H store + layer-2 scores)
    k_agg1<<<warpBlocks, WB>>>(b1);

    // GEMM2: X1H @ W2 -> fp16 XW2H
    k_hgemm<4, __half><<<(NN + 127) / 128, 256>>>(
        (const __half*)pX1H, (const __half*)pW2H, (const __half*)pW2L,
        nullptr, nullptr, NN, C1);

    // layer-2 aggregation + pool
    k_agg2<<<warpBlocks, WB>>>(b2);

    // FC over node rows + pooled rows -> entire output
    k_hgemm<1, float><<<(NN + BG + 127) / 128, 256>>>(
        (const float*)pX2E, (const __half*)pFWH, (const __half*)pFWL,
        fcb, out, NN + BG, DOUT);
}